// round 5
// baseline (speedup 1.0000x reference)
#include <cuda_runtime.h>
#include <math.h>

#define BATCH 2
#define SEQ   2048
#define EMB   1024
#define HEADS 16
#define HD    64
#define MROWS (BATCH*SEQ)   // 4096

// Scratch (allocation-free rule: __device__ globals). 16B-aligned for float4.
__device__ __align__(16) float g_q[BATCH*HEADS*SEQ*HD];
__device__ __align__(16) float g_k[BATCH*HEADS*SEQ*HD];
__device__ __align__(16) float g_v[BATCH*HEADS*SEQ*HD];
__device__ __align__(16) float g_attn[MROWS*EMB];

// ---------------------------------------------------------------------------
// Fused QKV projection: out[b,h,n,d] = (x @ W + bias) split into heads.
// 64x64 output tile, K-panel 16, 256 threads, 4x4 per thread.
// (Tile loads here cover 64x16 = 1024 floats = 256 threads x float4: complete.)
// ---------------------------------------------------------------------------
__global__ __launch_bounds__(256) void qkv_gemm_kernel(
    const float* __restrict__ x,
    const float* __restrict__ Wq, const float* __restrict__ bq,
    const float* __restrict__ Wk, const float* __restrict__ bk,
    const float* __restrict__ Wv, const float* __restrict__ bv)
{
    __shared__ float Ast[16][64];   // [k][m]  (transposed for float4 reads)
    __shared__ float Ws [16][64];   // [k][n]

    const int which = blockIdx.z;
    const float* __restrict__ W    = (which == 0) ? Wq : (which == 1) ? Wk : Wv;
    const float* __restrict__ bias = (which == 0) ? bq : (which == 1) ? bk : bv;
    float* __restrict__ outp       = (which == 0) ? g_q : (which == 1) ? g_k : g_v;

    const int m0 = blockIdx.y * 64;
    const int j0 = blockIdx.x * 64;
    const int tid = threadIdx.x;
    const int tx = tid & 15, ty = tid >> 4;

    const int arow = tid >> 2;          // 0..63  (A row within tile)
    const int acg  = (tid & 3) * 4;     // k-offset 0,4,8,12
    const int wrow = tid >> 4;          // 0..15  (W k-row)
    const int wcg  = (tid & 15) * 4;    // n-offset

    float acc[4][4] = {};

    for (int k0 = 0; k0 < EMB; k0 += 16) {
        float4 av = *(const float4*)&x[(size_t)(m0 + arow) * EMB + k0 + acg];
        float4 wv = *(const float4*)&W[(size_t)(k0 + wrow) * EMB + j0 + wcg];
        __syncthreads();
        Ast[acg + 0][arow] = av.x;
        Ast[acg + 1][arow] = av.y;
        Ast[acg + 2][arow] = av.z;
        Ast[acg + 3][arow] = av.w;
        *(float4*)&Ws[wrow][wcg] = wv;
        __syncthreads();
        #pragma unroll
        for (int k = 0; k < 16; ++k) {
            float a[4], b[4];
            *(float4*)a = *(const float4*)&Ast[k][ty * 4];
            *(float4*)b = *(const float4*)&Ws[k][tx * 4];
            #pragma unroll
            for (int r = 0; r < 4; ++r)
                #pragma unroll
                for (int c = 0; c < 4; ++c)
                    acc[r][c] = fmaf(a[r], b[c], acc[r][c]);
        }
    }

    // epilogue: bias + scatter into [B,H,N,D]
    const int j = j0 + tx * 4;
    const int h = j >> 6, d = j & 63;
    float b4[4];
    #pragma unroll
    for (int c = 0; c < 4; ++c) b4[c] = bias[j + c];
    #pragma unroll
    for (int r = 0; r < 4; ++r) {
        const int m = m0 + ty * 4 + r;
        const int bb = m >> 11;        // m / 2048
        const int n  = m & 2047;
        float4 o;
        o.x = acc[r][0] + b4[0];
        o.y = acc[r][1] + b4[1];
        o.z = acc[r][2] + b4[2];
        o.w = acc[r][3] + b4[3];
        *(float4*)&outp[(size_t)(((bb * HEADS) + h) * SEQ + n) * HD + d] = o;
    }
}

// ---------------------------------------------------------------------------
// Flash attention over one (64-row Q tile, head, batch).
// BUG FIX (R4->R5): tiles are 64x64 = 4096 floats; each of the 256 threads
// must load FOUR float4s (d0 = dc*16 + lcg, dc=0..3). Previous revisions
// loaded only one -> 3/4 of Qst/Kst/Vs was uninitialized smem (the source of
// the nondeterministic rel_err ~9.8 in R1-R4).
// ---------------------------------------------------------------------------
__global__ __launch_bounds__(256) void attention_kernel()
{
    extern __shared__ float smem[];
    float* Qst = smem;              // [64 d][64 i]
    float* Kst = smem + 4096;       // [64 d][64 j]   (reused as Ps[j][i])
    float* Vs  = smem + 8192;       // [64 j][64 d]

    const int tid = threadIdx.x;
    const int tx = tid & 15, ty = tid >> 4;
    const int qt = blockIdx.x;      // 0..31
    const int h  = blockIdx.y;
    const int b  = blockIdx.z;

    const float* __restrict__ qptr = g_q + (size_t)((b * HEADS + h) * SEQ) * HD;
    const float* __restrict__ kptr = g_k + (size_t)((b * HEADS + h) * SEQ) * HD;
    const float* __restrict__ vptr = g_v + (size_t)((b * HEADS + h) * SEQ) * HD;

    const int lrow = tid >> 2;        // 0..63
    const int lcg  = (tid & 3) * 4;   // 0,4,8,12

    // load Q tile (pre-scaled), transposed to [d][i] — FULL 64x64 coverage
    {
        const float scale = 0.125f;   // 1/sqrt(64)
        #pragma unroll
        for (int dc = 0; dc < 4; ++dc) {
            const int d0 = dc * 16 + lcg;
            float4 qv = *(const float4*)&qptr[(size_t)(qt * 64 + lrow) * HD + d0];
            Qst[(d0 + 0) * 64 + lrow] = qv.x * scale;
            Qst[(d0 + 1) * 64 + lrow] = qv.y * scale;
            Qst[(d0 + 2) * 64 + lrow] = qv.z * scale;
            Qst[(d0 + 3) * 64 + lrow] = qv.w * scale;
        }
    }

    float m_run[4], l_run[4];
    float acc[4][4] = {};
    #pragma unroll
    for (int r = 0; r < 4; ++r) { m_run[r] = -INFINITY; l_run[r] = 0.f; }

    for (int kt = 0; kt < 32; ++kt) {
        __syncthreads();   // prev PV done reading Vs/Ps; Q-load done (iter 0)
        {
            #pragma unroll
            for (int dc = 0; dc < 4; ++dc) {
                const int d0 = dc * 16 + lcg;
                float4 kv = *(const float4*)&kptr[(size_t)(kt * 64 + lrow) * HD + d0];
                Kst[(d0 + 0) * 64 + lrow] = kv.x;
                Kst[(d0 + 1) * 64 + lrow] = kv.y;
                Kst[(d0 + 2) * 64 + lrow] = kv.z;
                Kst[(d0 + 3) * 64 + lrow] = kv.w;
                float4 vv = *(const float4*)&vptr[(size_t)(kt * 64 + lrow) * HD + d0];
                *(float4*)&Vs[lrow * 64 + d0] = vv;
            }
        }
        __syncthreads();

        // S = (Q*scale) @ K^T   (4x4 per thread)
        float s[4][4] = {};
        #pragma unroll 8
        for (int d = 0; d < 64; ++d) {
            float a[4], kk[4];
            *(float4*)a  = *(const float4*)&Qst[d * 64 + ty * 4];
            *(float4*)kk = *(const float4*)&Kst[d * 64 + tx * 4];
            #pragma unroll
            for (int r = 0; r < 4; ++r)
                #pragma unroll
                for (int c = 0; c < 4; ++c)
                    s[r][c] = fmaf(a[r], kk[c], s[r][c]);
        }

        // online softmax: row reductions across the 16 tx-threads
        float mt[4], p[4][4], rs[4];
        #pragma unroll
        for (int r = 0; r < 4; ++r)
            mt[r] = fmaxf(fmaxf(s[r][0], s[r][1]), fmaxf(s[r][2], s[r][3]));
        #pragma unroll
        for (int r = 0; r < 4; ++r) {
            #pragma unroll
            for (int mask = 1; mask <= 8; mask <<= 1)
                mt[r] = fmaxf(mt[r], __shfl_xor_sync(0xffffffffu, mt[r], mask));
        }
        #pragma unroll
        for (int r = 0; r < 4; ++r) {
            float mn = fmaxf(m_run[r], mt[r]);
            float alpha = __expf(m_run[r] - mn);   // exp(-inf)=0 on first tile
            m_run[r] = mn;
            rs[r] = 0.f;
            #pragma unroll
            for (int c = 0; c < 4; ++c) {
                p[r][c] = __expf(s[r][c] - mn);
                rs[r] += p[r][c];
            }
            l_run[r] *= alpha;
            #pragma unroll
            for (int c = 0; c < 4; ++c) acc[r][c] *= alpha;
        }
        #pragma unroll
        for (int r = 0; r < 4; ++r) {
            #pragma unroll
            for (int mask = 1; mask <= 8; mask <<= 1)
                rs[r] += __shfl_xor_sync(0xffffffffu, rs[r], mask);
            l_run[r] += rs[r];
        }

        __syncthreads();          // everyone done reading Kst
        float* Ps = Kst;          // alias: Ps[j][i]
        #pragma unroll
        for (int r = 0; r < 4; ++r)
            #pragma unroll
            for (int c = 0; c < 4; ++c)
                Ps[(tx * 4 + c) * 64 + ty * 4 + r] = p[r][c];
        __syncthreads();

        // O += P @ V
        #pragma unroll 8
        for (int j = 0; j < 64; ++j) {
            float pa[4], vv[4];
            *(float4*)pa = *(const float4*)&Ps[j * 64 + ty * 4];
            *(float4*)vv = *(const float4*)&Vs[j * 64 + tx * 4];
            #pragma unroll
            for (int r = 0; r < 4; ++r)
                #pragma unroll
                for (int c = 0; c < 4; ++c)
                    acc[r][c] = fmaf(pa[r], vv[c], acc[r][c]);
        }
    }

    // write O / l  into [B, N, H*D]
    #pragma unroll
    for (int r = 0; r < 4; ++r) {
        const float inv = 1.0f / l_run[r];
        const int iG = qt * 64 + ty * 4 + r;
        float4 o;
        o.x = acc[r][0] * inv;
        o.y = acc[r][1] * inv;
        o.z = acc[r][2] * inv;
        o.w = acc[r][3] * inv;
        *(float4*)&g_attn[(size_t)(b * SEQ + iG) * EMB + h * HD + tx * 4] = o;
    }
}

// ---------------------------------------------------------------------------
// Output projection: out = g_attn @ Wo + bo
// ---------------------------------------------------------------------------
__global__ __launch_bounds__(256) void out_gemm_kernel(
    const float* __restrict__ Wo, const float* __restrict__ bo,
    float* __restrict__ out)
{
    __shared__ float Ast[16][64];
    __shared__ float Ws [16][64];

    const int m0 = blockIdx.y * 64;
    const int j0 = blockIdx.x * 64;
    const int tid = threadIdx.x;
    const int tx = tid & 15, ty = tid >> 4;

    const int arow = tid >> 2;
    const int acg  = (tid & 3) * 4;
    const int wrow = tid >> 4;
    const int wcg  = (tid & 15) * 4;

    float acc[4][4] = {};

    for (int k0 = 0; k0 < EMB; k0 += 16) {
        float4 av = *(const float4*)&g_attn[(size_t)(m0 + arow) * EMB + k0 + acg];
        float4 wv = *(const float4*)&Wo[(size_t)(k0 + wrow) * EMB + j0 + wcg];
        __syncthreads();
        Ast[acg + 0][arow] = av.x;
        Ast[acg + 1][arow] = av.y;
        Ast[acg + 2][arow] = av.z;
        Ast[acg + 3][arow] = av.w;
        *(float4*)&Ws[wrow][wcg] = wv;
        __syncthreads();
        #pragma unroll
        for (int k = 0; k < 16; ++k) {
            float a[4], b[4];
            *(float4*)a = *(const float4*)&Ast[k][ty * 4];
            *(float4*)b = *(const float4*)&Ws[k][tx * 4];
            #pragma unroll
            for (int r = 0; r < 4; ++r)
                #pragma unroll
                for (int c = 0; c < 4; ++c)
                    acc[r][c] = fmaf(a[r], b[c], acc[r][c]);
        }
    }

    const int j = j0 + tx * 4;
    float b4[4];
    #pragma unroll
    for (int c = 0; c < 4; ++c) b4[c] = bo[j + c];
    #pragma unroll
    for (int r = 0; r < 4; ++r) {
        const int m = m0 + ty * 4 + r;
        float4 o;
        o.x = acc[r][0] + b4[0];
        o.y = acc[r][1] + b4[1];
        o.z = acc[r][2] + b4[2];
        o.w = acc[r][3] + b4[3];
        *(float4*)&out[(size_t)m * EMB + j] = o;
    }
}

// ---------------------------------------------------------------------------
// Unit-agnostic, UB-free input dispatch (proven robust in R4; unchanged).
// ---------------------------------------------------------------------------
extern "C" void kernel_launch(void* const* d_in, const int* in_sizes, int n_in,
                              void* d_out, int out_size)
{
    (void)out_size;

    long long scale = 1;
    for (int i = 0; i < n_in; ++i)
        if ((long long)in_sizes[i] == 16777216LL) { scale = 4; break; }

    // safe positional defaults (insertion order: x,Wq,bq,Wk,bk,Wv,bv,Wo,bo)
    const float* x  = (const float*)d_in[0];
    const float* Wenc[4] = { (const float*)d_in[1], (const float*)d_in[3],
                             (const float*)d_in[5], (const float*)d_in[7] };
    const float* benc[4] = { (const float*)d_in[2], (const float*)d_in[4],
                             (const float*)d_in[6], (const float*)d_in[8] };
    int wIdx[4] = { 1, 3, 5, 7 };
    int nw = 0, nb = 0;

    for (int i = 0; i < n_in; ++i) {
        long long elems = (long long)in_sizes[i] / scale;
        if (elems == (long long)BATCH * SEQ * EMB) {
            x = (const float*)d_in[i];
        } else if (elems == (long long)EMB * EMB) {
            if (nw < 4) { wIdx[nw] = i; Wenc[nw] = (const float*)d_in[i]; }
            ++nw;
        } else if (elems == (long long)EMB) {
            if (nb < 4) { benc[nb] = (const float*)d_in[i]; }
            ++nb;
        }
    }

    bool sortedLayout = false;
    if (nw == 4 && nb == 4)
        sortedLayout = (wIdx[1] == wIdx[0] + 1) &&
                       (wIdx[2] == wIdx[1] + 1) &&
                       (wIdx[3] == wIdx[2] + 1);

    const float *Wq, *Wk, *Wv, *Wo, *bq, *bk, *bv, *bo;
    if (sortedLayout) {
        // any ascending name sort: W/b encounter order = k, o, q, v
        Wk = Wenc[0]; Wo = Wenc[1]; Wq = Wenc[2]; Wv = Wenc[3];
        bk = benc[0]; bo = benc[1]; bq = benc[2]; bv = benc[3];
    } else {
        // insertion order: q, k, v, o
        Wq = Wenc[0]; Wk = Wenc[1]; Wv = Wenc[2]; Wo = Wenc[3];
        bq = benc[0]; bk = benc[1]; bv = benc[2]; bo = benc[3];
    }

    float* out = (float*)d_out;

    qkv_gemm_kernel<<<dim3(EMB / 64, MROWS / 64, 3), 256>>>(
        x, Wq, bq, Wk, bk, Wv, bv);

    attention_kernel<<<dim3(SEQ / 64, HEADS, BATCH), 256,
                       3 * 64 * 64 * sizeof(float)>>>();

    out_gemm_kernel<<<dim3(EMB / 64, MROWS / 64), 256>>>(Wo, bo, out);
}

// round 7
// speedup vs baseline: 1.3626x; 1.3626x over previous
#include <cuda_runtime.h>
#include <cuda_bf16.h>
#include <math.h>
#include <stdint.h>

#define BATCH 2
#define SEQ   2048
#define EMB   1024
#define HEADS 16
#define HD    64
#define MROWS (BATCH*SEQ)   // 4096

// ---------------------------------------------------------------------------
// Scratch (__device__ globals; allocation-free rule)
// ---------------------------------------------------------------------------
__device__ __align__(16) float g_q[BATCH*HEADS*SEQ*HD];
__device__ __align__(16) float g_k[BATCH*HEADS*SEQ*HD];
__device__ __align__(16) float g_v[BATCH*HEADS*SEQ*HD];
__device__ __align__(16) float g_attn[MROWS*EMB];

__device__ __align__(16) __nv_bfloat16 g_xh[MROWS*EMB];
__device__ __align__(16) __nv_bfloat16 g_xl[MROWS*EMB];
__device__ __align__(16) __nv_bfloat16 g_wth[4u*EMB*EMB];   // W^T hi: q,k,v,o
__device__ __align__(16) __nv_bfloat16 g_wtl[4u*EMB*EMB];   // W^T lo
__device__ __align__(16) __nv_bfloat16 g_ah[MROWS*EMB];     // attn hi
__device__ __align__(16) __nv_bfloat16 g_al[MROWS*EMB];     // attn lo

// ---------------------------------------------------------------------------
// warp-MMA helpers (plain sm_80+ PTX: assembles for compute_100)
// ---------------------------------------------------------------------------
__device__ __forceinline__ uint32_t smem_u32(const void* p) {
    uint32_t a;
    asm("{ .reg .u64 t; cvta.to.shared.u64 t, %1; cvt.u32.u64 %0, t; }"
        : "=r"(a) : "l"(p));
    return a;
}
__device__ __forceinline__ void ldsm_x4(uint32_t& r0, uint32_t& r1,
                                        uint32_t& r2, uint32_t& r3, uint32_t a) {
    asm volatile("ldmatrix.sync.aligned.m8n8.x4.shared.b16 {%0,%1,%2,%3}, [%4];"
                 : "=r"(r0), "=r"(r1), "=r"(r2), "=r"(r3) : "r"(a));
}
__device__ __forceinline__ void mma_bf16(float* d, const uint32_t* a,
                                         uint32_t b0, uint32_t b1) {
    asm volatile("mma.sync.aligned.m16n8k16.row.col.f32.bf16.bf16.f32 "
                 "{%0,%1,%2,%3}, {%4,%5,%6,%7}, {%8,%9}, {%0,%1,%2,%3};"
                 : "+f"(d[0]), "+f"(d[1]), "+f"(d[2]), "+f"(d[3])
                 : "r"(a[0]), "r"(a[1]), "r"(a[2]), "r"(a[3]), "r"(b0), "r"(b1));
}
__device__ __forceinline__ uint32_t swz(uint32_t o) { return o ^ ((o >> 3) & 0x70); }

// ---------------------------------------------------------------------------
// split helpers
// ---------------------------------------------------------------------------
__device__ __forceinline__ void split2(float a, unsigned short& h, unsigned short& l) {
    __nv_bfloat16 hb = __float2bfloat16_rn(a);
    __nv_bfloat16 lb = __float2bfloat16_rn(a - __bfloat162float(hb));
    h = __bfloat16_as_ushort(hb);
    l = __bfloat16_as_ushort(lb);
}

__global__ __launch_bounds__(256) void cvt_x_kernel(const float* __restrict__ src) {
    int i = blockIdx.x * 256 + threadIdx.x;
    float4 v = ((const float4*)src)[i];
    ushort4 h, l;
    split2(v.x, h.x, l.x); split2(v.y, h.y, l.y);
    split2(v.z, h.z, l.z); split2(v.w, h.w, l.w);
    ((ushort4*)g_xh)[i] = h;
    ((ushort4*)g_xl)[i] = l;
}
__global__ __launch_bounds__(256) void cvt_attn_kernel() {
    int i = blockIdx.x * 256 + threadIdx.x;
    float4 v = ((const float4*)g_attn)[i];
    ushort4 h, l;
    split2(v.x, h.x, l.x); split2(v.y, h.y, l.y);
    split2(v.z, h.z, l.z); split2(v.w, h.w, l.w);
    ((ushort4*)g_ah)[i] = h;
    ((ushort4*)g_al)[i] = l;
}

// W[k][n] -> W^T[n][k] hi/lo; z selects q,k,v,o
__global__ __launch_bounds__(256) void transpose_cvt_kernel(
    const float* __restrict__ Wq, const float* __restrict__ Wk,
    const float* __restrict__ Wv, const float* __restrict__ Wo)
{
    const float* __restrict__ src =
        (blockIdx.z == 0) ? Wq : (blockIdx.z == 1) ? Wk : (blockIdx.z == 2) ? Wv : Wo;
    __shared__ float t[32][33];
    const int tx = threadIdx.x & 31, ty = threadIdx.x >> 5;
    const int k0 = blockIdx.x * 32, n0 = blockIdx.y * 32;
    #pragma unroll
    for (int i = 0; i < 4; ++i) {
        int r = ty + i * 8;
        t[r][tx] = src[(size_t)(k0 + r) * EMB + n0 + tx];
    }
    __syncthreads();
    const size_t base = (size_t)blockIdx.z * EMB * EMB;
    #pragma unroll
    for (int i = 0; i < 4; ++i) {
        int r = ty + i * 8;
        float a = t[tx][r];
        unsigned short h, l;
        split2(a, h, l);
        size_t o = base + (size_t)(n0 + r) * EMB + k0 + tx;
        g_wth[o] = __ushort_as_bfloat16(h);
        g_wtl[o] = __ushort_as_bfloat16(l);
    }
}

// ---------------------------------------------------------------------------
// split-bf16 HMMA GEMM: D[M x 1024] = A @ B^T (+bias), B^T stored [N][K].
// CTA tile 128x128, K-chunk 64. 8 warps in 2(m) x 4(n); warp tile 64x32.
// Terms: ah*bh + ah*bl + al*bh  (fp32 accum) -> rel err ~1e-5.
// mode 0: QKV (z selects weights/bias; scatter to g_q/g_k/g_v [B,H,N,D])
// mode 1: out projection (row-major to out0)
// ---------------------------------------------------------------------------
#define SMEM_A_HI 0
#define SMEM_A_LO 16384
#define SMEM_B_HI 32768
#define SMEM_B_LO 49152
#define SMEM_DYN  65536

__global__ __launch_bounds__(256, 1) void mma_gemm_kernel(
    const float* __restrict__ b0i, const float* __restrict__ b1i,
    const float* __restrict__ b2i, float* __restrict__ out0, int mode)
{
    extern __shared__ char smem[];
    const int tid = threadIdx.x, wid = tid >> 5, lid = tid & 31;
    const int n0 = blockIdx.x * 128, m0 = blockIdx.y * 128;
    const int z = blockIdx.z;

    const __nv_bfloat16 *Ah, *Al, *Bh, *Bl;
    const float* bias;
    if (mode == 0) {
        Ah = g_xh; Al = g_xl;
        Bh = g_wth + (size_t)z * EMB * EMB;
        Bl = g_wtl + (size_t)z * EMB * EMB;
        bias = (z == 0) ? b0i : (z == 1) ? b1i : b2i;
    } else {
        Ah = g_ah; Al = g_al;
        Bh = g_wth + 3ull * EMB * EMB;
        Bl = g_wtl + 3ull * EMB * EMB;
        bias = b0i;
    }

    const uint32_t sb = smem_u32(smem);
    const int wm0 = (wid >> 2) * 64;     // warp m-offset in tile
    const int wn0 = (wid & 3) * 32;      // warp n-offset in tile

    float acc[4][4][4] = {};             // [mi][ni][frag]

    for (int ch = 0; ch < 16; ++ch) {
        const int k0 = ch * 64;
        __syncthreads();                 // prev chunk's ldmatrix done
        #pragma unroll
        for (int i = 0; i < 4; ++i) {
            const int idx = tid + i * 256;          // 0..1023
            const int r = idx >> 3, c = idx & 7;    // row, 16B chunk
            const uint32_t sw = swz((uint32_t)(r * 128 + c * 16));
            const size_t ga = (size_t)(m0 + r) * EMB + k0 + c * 8;
            const size_t gb = (size_t)(n0 + r) * EMB + k0 + c * 8;
            *(int4*)(smem + SMEM_A_HI + sw) = *(const int4*)(Ah + ga);
            *(int4*)(smem + SMEM_A_LO + sw) = *(const int4*)(Al + ga);
            *(int4*)(smem + SMEM_B_HI + sw) = *(const int4*)(Bh + gb);
            *(int4*)(smem + SMEM_B_LO + sw) = *(const int4*)(Bl + gb);
        }
        __syncthreads();

        #pragma unroll
        for (int k16 = 0; k16 < 4; ++k16) {
            const uint32_t colB = (uint32_t)(k16 * 32 + (lid >> 4) * 16);

            // B fragments: 2 ldmatrix.x4 per hi/lo covering 4 n8-tiles
            uint32_t bh[4][2], bl[4][2];
            #pragma unroll
            for (int p = 0; p < 2; ++p) {
                const uint32_t off = swz((uint32_t)((wn0 + p * 16 + (lid & 15)) * 128) ^ colB);
                // note: swz(row*128 + colB) == swz on combined offset; colB<128 so add==xor
                uint32_t r0, r1, r2, r3;
                ldsm_x4(r0, r1, r2, r3, sb + SMEM_B_HI + off);
                bh[2*p][0] = r0; bh[2*p][1] = r2;
                bh[2*p+1][0] = r1; bh[2*p+1][1] = r3;
                ldsm_x4(r0, r1, r2, r3, sb + SMEM_B_LO + off);
                bl[2*p][0] = r0; bl[2*p][1] = r2;
                bl[2*p+1][0] = r1; bl[2*p+1][1] = r3;
            }

            #pragma unroll
            for (int mi = 0; mi < 4; ++mi) {
                const uint32_t offA = swz((uint32_t)((wm0 + mi * 16 + (lid & 15)) * 128) ^ colB);
                uint32_t ahf[4], alf[4];
                ldsm_x4(ahf[0], ahf[1], ahf[2], ahf[3], sb + SMEM_A_HI + offA);
                ldsm_x4(alf[0], alf[1], alf[2], alf[3], sb + SMEM_A_LO + offA);
                #pragma unroll
                for (int ni = 0; ni < 4; ++ni) {
                    mma_bf16(acc[mi][ni], ahf, bh[ni][0], bh[ni][1]);
                    mma_bf16(acc[mi][ni], ahf, bl[ni][0], bl[ni][1]);
                    mma_bf16(acc[mi][ni], alf, bh[ni][0], bh[ni][1]);
                }
            }
        }
    }

    // epilogue: bias + store (accum frag: d0,d1 = row r, cols c,c+1; d2,d3 = row r+8)
    const int rr = lid >> 2;             // 0..7
    const int cc = (lid & 3) * 2;        // 0,2,4,6
    #pragma unroll
    for (int mi = 0; mi < 4; ++mi) {
        #pragma unroll
        for (int ni = 0; ni < 4; ++ni) {
            const int gcol = n0 + wn0 + ni * 8 + cc;
            const float bx = bias[gcol], by = bias[gcol + 1];
            #pragma unroll
            for (int half = 0; half < 2; ++half) {
                const int m = m0 + wm0 + mi * 16 + rr + half * 8;
                float2 o;
                o.x = acc[mi][ni][half * 2 + 0] + bx;
                o.y = acc[mi][ni][half * 2 + 1] + by;
                if (mode == 0) {
                    const int bb = m >> 11, nn = m & 2047;
                    const int h = gcol >> 6, dd = gcol & 63;
                    float* op = ((z == 0) ? g_q : (z == 1) ? g_k : g_v)
                                + ((size_t)(bb * HEADS + h) * SEQ + nn) * HD + dd;
                    *(float2*)op = o;
                } else {
                    *(float2*)&out0[(size_t)m * EMB + gcol] = o;
                }
            }
        }
    }
}

// ---------------------------------------------------------------------------
// Flash attention (fp32, unchanged — proven correct in R5)
// ---------------------------------------------------------------------------
__global__ __launch_bounds__(256) void attention_kernel()
{
    extern __shared__ float smf[];
    float* Qst = smf;               // [64 d][64 i]
    float* Kst = smf + 4096;        // [64 d][64 j]  (reused as Ps[j][i])
    float* Vs  = smf + 8192;        // [64 j][64 d]

    const int tid = threadIdx.x;
    const int tx = tid & 15, ty = tid >> 4;
    const int qt = blockIdx.x, h = blockIdx.y, b = blockIdx.z;

    const float* __restrict__ qptr = g_q + (size_t)((b * HEADS + h) * SEQ) * HD;
    const float* __restrict__ kptr = g_k + (size_t)((b * HEADS + h) * SEQ) * HD;
    const float* __restrict__ vptr = g_v + (size_t)((b * HEADS + h) * SEQ) * HD;

    const int lrow = tid >> 2;
    const int lcg  = (tid & 3) * 4;

    {
        const float scale = 0.125f;
        #pragma unroll
        for (int dc = 0; dc < 4; ++dc) {
            const int d0 = dc * 16 + lcg;
            float4 qv = *(const float4*)&qptr[(size_t)(qt * 64 + lrow) * HD + d0];
            Qst[(d0 + 0) * 64 + lrow] = qv.x * scale;
            Qst[(d0 + 1) * 64 + lrow] = qv.y * scale;
            Qst[(d0 + 2) * 64 + lrow] = qv.z * scale;
            Qst[(d0 + 3) * 64 + lrow] = qv.w * scale;
        }
    }

    float m_run[4], l_run[4];
    float acc[4][4] = {};
    #pragma unroll
    for (int r = 0; r < 4; ++r) { m_run[r] = -INFINITY; l_run[r] = 0.f; }

    for (int kt = 0; kt < 32; ++kt) {
        __syncthreads();
        {
            #pragma unroll
            for (int dc = 0; dc < 4; ++dc) {
                const int d0 = dc * 16 + lcg;
                float4 kv = *(const float4*)&kptr[(size_t)(kt * 64 + lrow) * HD + d0];
                Kst[(d0 + 0) * 64 + lrow] = kv.x;
                Kst[(d0 + 1) * 64 + lrow] = kv.y;
                Kst[(d0 + 2) * 64 + lrow] = kv.z;
                Kst[(d0 + 3) * 64 + lrow] = kv.w;
                float4 vv = *(const float4*)&vptr[(size_t)(kt * 64 + lrow) * HD + d0];
                *(float4*)&Vs[lrow * 64 + d0] = vv;
            }
        }
        __syncthreads();

        float s[4][4] = {};
        #pragma unroll 8
        for (int d = 0; d < 64; ++d) {
            float a[4], kk[4];
            *(float4*)a  = *(const float4*)&Qst[d * 64 + ty * 4];
            *(float4*)kk = *(const float4*)&Kst[d * 64 + tx * 4];
            #pragma unroll
            for (int r = 0; r < 4; ++r)
                #pragma unroll
                for (int c = 0; c < 4; ++c)
                    s[r][c] = fmaf(a[r], kk[c], s[r][c]);
        }

        float mt[4], p[4][4], rs[4];
        #pragma unroll
        for (int r = 0; r < 4; ++r)
            mt[r] = fmaxf(fmaxf(s[r][0], s[r][1]), fmaxf(s[r][2], s[r][3]));
        #pragma unroll
        for (int r = 0; r < 4; ++r) {
            #pragma unroll
            for (int mask = 1; mask <= 8; mask <<= 1)
                mt[r] = fmaxf(mt[r], __shfl_xor_sync(0xffffffffu, mt[r], mask));
        }
        #pragma unroll
        for (int r = 0; r < 4; ++r) {
            float mn = fmaxf(m_run[r], mt[r]);
            float alpha = __expf(m_run[r] - mn);
            m_run[r] = mn;
            rs[r] = 0.f;
            #pragma unroll
            for (int c = 0; c < 4; ++c) {
                p[r][c] = __expf(s[r][c] - mn);
                rs[r] += p[r][c];
            }
            l_run[r] *= alpha;
            #pragma unroll
            for (int c = 0; c < 4; ++c) acc[r][c] *= alpha;
        }
        #pragma unroll
        for (int r = 0; r < 4; ++r) {
            #pragma unroll
            for (int mask = 1; mask <= 8; mask <<= 1)
                rs[r] += __shfl_xor_sync(0xffffffffu, rs[r], mask);
            l_run[r] += rs[r];
        }

        __syncthreads();
        float* Ps = Kst;
        #pragma unroll
        for (int r = 0; r < 4; ++r)
            #pragma unroll
            for (int c = 0; c < 4; ++c)
                Ps[(tx * 4 + c) * 64 + ty * 4 + r] = p[r][c];
        __syncthreads();

        #pragma unroll 8
        for (int j = 0; j < 64; ++j) {
            float pa[4], vv[4];
            *(float4*)pa = *(const float4*)&Ps[j * 64 + ty * 4];
            *(float4*)vv = *(const float4*)&Vs[j * 64 + tx * 4];
            #pragma unroll
            for (int r = 0; r < 4; ++r)
                #pragma unroll
                for (int c = 0; c < 4; ++c)
                    acc[r][c] = fmaf(pa[r], vv[c], acc[r][c]);
        }
    }

    #pragma unroll
    for (int r = 0; r < 4; ++r) {
        const float inv = 1.0f / l_run[r];
        const int iG = qt * 64 + ty * 4 + r;
        float4 o;
        o.x = acc[r][0] * inv;
        o.y = acc[r][1] * inv;
        o.z = acc[r][2] * inv;
        o.w = acc[r][3] * inv;
        *(float4*)&g_attn[(size_t)(b * SEQ + iG) * EMB + h * HD + tx * 4] = o;
    }
}

// ---------------------------------------------------------------------------
// Dispatch (robust size-class mapping, proven in R4/R5)
// ---------------------------------------------------------------------------
extern "C" void kernel_launch(void* const* d_in, const int* in_sizes, int n_in,
                              void* d_out, int out_size)
{
    (void)out_size;

    long long scale = 1;
    for (int i = 0; i < n_in; ++i)
        if ((long long)in_sizes[i] == 16777216LL) { scale = 4; break; }

    const float* x  = (const float*)d_in[0];
    const float* Wenc[4] = { (const float*)d_in[1], (const float*)d_in[3],
                             (const float*)d_in[5], (const float*)d_in[7] };
    const float* benc[4] = { (const float*)d_in[2], (const float*)d_in[4],
                             (const float*)d_in[6], (const float*)d_in[8] };
    int wIdx[4] = { 1, 3, 5, 7 };
    int nw = 0, nb = 0;

    for (int i = 0; i < n_in; ++i) {
        long long elems = (long long)in_sizes[i] / scale;
        if (elems == (long long)BATCH * SEQ * EMB) {
            x = (const float*)d_in[i];
        } else if (elems == (long long)EMB * EMB) {
            if (nw < 4) { wIdx[nw] = i; Wenc[nw] = (const float*)d_in[i]; }
            ++nw;
        } else if (elems == (long long)EMB) {
            if (nb < 4) { benc[nb] = (const float*)d_in[i]; }
            ++nb;
        }
    }

    bool sortedLayout = false;
    if (nw == 4 && nb == 4)
        sortedLayout = (wIdx[1] == wIdx[0] + 1) &&
                       (wIdx[2] == wIdx[1] + 1) &&
                       (wIdx[3] == wIdx[2] + 1);

    const float *Wq, *Wk, *Wv, *Wo, *bq, *bk, *bv, *bo;
    if (sortedLayout) {
        Wk = Wenc[0]; Wo = Wenc[1]; Wq = Wenc[2]; Wv = Wenc[3];
        bk = benc[0]; bo = benc[1]; bq = benc[2]; bv = benc[3];
    } else {
        Wq = Wenc[0]; Wk = Wenc[1]; Wv = Wenc[2]; Wo = Wenc[3];
        bq = benc[0]; bk = benc[1]; bv = benc[2]; bo = benc[3];
    }

    float* out = (float*)d_out;

    cudaFuncSetAttribute(mma_gemm_kernel,
                         cudaFuncAttributeMaxDynamicSharedMemorySize, SMEM_DYN);

    // 0) split conversions
    cvt_x_kernel<<<MROWS * EMB / 1024, 256>>>(x);
    transpose_cvt_kernel<<<dim3(EMB / 32, EMB / 32, 4), 256>>>(Wq, Wk, Wv, Wo);

    // 1) QKV projections (HMMA split-bf16)
    mma_gemm_kernel<<<dim3(EMB / 128, MROWS / 128, 3), 256, SMEM_DYN>>>(
        bq, bk, bv, nullptr, 0);

    // 2) flash attention (fp32)
    attention_kernel<<<dim3(SEQ / 64, HEADS, BATCH), 256,
                       3 * 64 * 64 * sizeof(float)>>>();

    // 3) output projection (HMMA split-bf16)
    cvt_attn_kernel<<<MROWS * EMB / 1024, 256>>>();
    mma_gemm_kernel<<<dim3(EMB / 128, MROWS / 128, 1), 256, SMEM_DYN>>>(
        bo, bo, bo, out, 1);
}

// round 8
// speedup vs baseline: 2.7154x; 1.9928x over previous
#include <cuda_runtime.h>
#include <cuda_bf16.h>
#include <math.h>
#include <stdint.h>

#define BATCH 2
#define SEQ   2048
#define EMB   1024
#define HEADS 16
#define HD    64
#define MROWS (BATCH*SEQ)   // 4096

// ---------------------------------------------------------------------------
// Scratch (__device__ globals; allocation-free rule)
// ---------------------------------------------------------------------------
__device__ __align__(16) __nv_bfloat16 g_xh[MROWS*EMB];
__device__ __align__(16) __nv_bfloat16 g_xl[MROWS*EMB];
__device__ __align__(16) __nv_bfloat16 g_wth[4u*EMB*EMB];   // W^T hi: q,k,v,o
__device__ __align__(16) __nv_bfloat16 g_wtl[4u*EMB*EMB];   // W^T lo
__device__ __align__(16) __nv_bfloat16 g_qh[BATCH*HEADS*SEQ*HD];  // pre-scaled 1/8
__device__ __align__(16) __nv_bfloat16 g_ql[BATCH*HEADS*SEQ*HD];
__device__ __align__(16) __nv_bfloat16 g_kh[BATCH*HEADS*SEQ*HD];
__device__ __align__(16) __nv_bfloat16 g_kl[BATCH*HEADS*SEQ*HD];
__device__ __align__(16) __nv_bfloat16 g_vh[BATCH*HEADS*SEQ*HD];
__device__ __align__(16) __nv_bfloat16 g_vl[BATCH*HEADS*SEQ*HD];
__device__ __align__(16) __nv_bfloat16 g_ah[MROWS*EMB];     // attn out hi
__device__ __align__(16) __nv_bfloat16 g_al[MROWS*EMB];     // attn out lo

// ---------------------------------------------------------------------------
// PTX helpers (sm_80+ subset: assembles for compute_100)
// ---------------------------------------------------------------------------
__device__ __forceinline__ uint32_t smem_u32(const void* p) {
    uint32_t a;
    asm("{ .reg .u64 t; cvta.to.shared.u64 t, %1; cvt.u32.u64 %0, t; }"
        : "=r"(a) : "l"(p));
    return a;
}
__device__ __forceinline__ void ldsm_x4(uint32_t& r0, uint32_t& r1,
                                        uint32_t& r2, uint32_t& r3, uint32_t a) {
    asm volatile("ldmatrix.sync.aligned.m8n8.x4.shared.b16 {%0,%1,%2,%3}, [%4];"
                 : "=r"(r0), "=r"(r1), "=r"(r2), "=r"(r3) : "r"(a));
}
__device__ __forceinline__ void ldsm_x4_t(uint32_t& r0, uint32_t& r1,
                                          uint32_t& r2, uint32_t& r3, uint32_t a) {
    asm volatile("ldmatrix.sync.aligned.m8n8.x4.trans.shared.b16 {%0,%1,%2,%3}, [%4];"
                 : "=r"(r0), "=r"(r1), "=r"(r2), "=r"(r3) : "r"(a));
}
__device__ __forceinline__ void mma_bf16(float* d, const uint32_t* a,
                                         uint32_t b0, uint32_t b1) {
    asm volatile("mma.sync.aligned.m16n8k16.row.col.f32.bf16.bf16.f32 "
                 "{%0,%1,%2,%3}, {%4,%5,%6,%7}, {%8,%9}, {%0,%1,%2,%3};"
                 : "+f"(d[0]), "+f"(d[1]), "+f"(d[2]), "+f"(d[3])
                 : "r"(a[0]), "r"(a[1]), "r"(a[2]), "r"(a[3]), "r"(b0), "r"(b1));
}
__device__ __forceinline__ void cp16(uint32_t dst, const void* src) {
    asm volatile("cp.async.cg.shared.global [%0], [%1], 16;"
                 :: "r"(dst), "l"(src) : "memory");
}
#define CP_COMMIT() asm volatile("cp.async.commit_group;" ::: "memory")
#define CP_WAIT(N)  asm volatile("cp.async.wait_group %0;" :: "n"(N) : "memory")

__device__ __forceinline__ uint32_t swz(uint32_t o) { return o ^ ((o >> 3) & 0x70); }

__device__ __forceinline__ void split2(float a, unsigned short& h, unsigned short& l) {
    __nv_bfloat16 hb = __float2bfloat16_rn(a);
    __nv_bfloat16 lb = __float2bfloat16_rn(a - __bfloat162float(hb));
    h = __bfloat16_as_ushort(hb);
    l = __bfloat16_as_ushort(lb);
}
// pack (lo -> low halfword, hi -> high halfword)
__device__ __forceinline__ uint32_t packlh(float lo, float hi) {
    uint32_t r;
    asm("cvt.rn.bf16x2.f32 %0, %1, %2;" : "=r"(r) : "f"(hi), "f"(lo));
    return r;
}

// ---------------------------------------------------------------------------
// conversion kernels
// ---------------------------------------------------------------------------
__global__ __launch_bounds__(256) void cvt_x_kernel(const float* __restrict__ src) {
    int i = blockIdx.x * 256 + threadIdx.x;
    float4 v = ((const float4*)src)[i];
    ushort4 h, l;
    split2(v.x, h.x, l.x); split2(v.y, h.y, l.y);
    split2(v.z, h.z, l.z); split2(v.w, h.w, l.w);
    ((ushort4*)g_xh)[i] = h;
    ((ushort4*)g_xl)[i] = l;
}
__global__ __launch_bounds__(256) void transpose_cvt_kernel(
    const float* __restrict__ Wq, const float* __restrict__ Wk,
    const float* __restrict__ Wv, const float* __restrict__ Wo)
{
    const float* __restrict__ src =
        (blockIdx.z == 0) ? Wq : (blockIdx.z == 1) ? Wk : (blockIdx.z == 2) ? Wv : Wo;
    __shared__ float t[32][33];
    const int tx = threadIdx.x & 31, ty = threadIdx.x >> 5;
    const int k0 = blockIdx.x * 32, n0 = blockIdx.y * 32;
    #pragma unroll
    for (int i = 0; i < 4; ++i) {
        int r = ty + i * 8;
        t[r][tx] = src[(size_t)(k0 + r) * EMB + n0 + tx];
    }
    __syncthreads();
    const size_t base = (size_t)blockIdx.z * EMB * EMB;
    #pragma unroll
    for (int i = 0; i < 4; ++i) {
        int r = ty + i * 8;
        float a = t[tx][r];
        unsigned short h, l;
        split2(a, h, l);
        size_t o = base + (size_t)(n0 + r) * EMB + k0 + tx;
        g_wth[o] = __ushort_as_bfloat16(h);
        g_wtl[o] = __ushort_as_bfloat16(l);
    }
}

// ---------------------------------------------------------------------------
// split-bf16 HMMA GEMM (structure verified in R7). Epilogue:
// mode 0: write split-bf16 q/k/v in [b,h,token,d]; Q pre-scaled by 1/8.
// mode 1: fp32 row-major to out0 (+bias).
// ---------------------------------------------------------------------------
#define SMEM_A_HI 0
#define SMEM_A_LO 16384
#define SMEM_B_HI 32768
#define SMEM_B_LO 49152
#define SMEM_DYN  65536

__global__ __launch_bounds__(256, 1) void mma_gemm_kernel(
    const float* __restrict__ b0i, const float* __restrict__ b1i,
    const float* __restrict__ b2i, float* __restrict__ out0, int mode)
{
    extern __shared__ char smem[];
    const int tid = threadIdx.x, wid = tid >> 5, lid = tid & 31;
    const int n0 = blockIdx.x * 128, m0 = blockIdx.y * 128;
    const int z = blockIdx.z;

    const __nv_bfloat16 *Ah, *Al, *Bh, *Bl;
    const float* bias;
    if (mode == 0) {
        Ah = g_xh; Al = g_xl;
        Bh = g_wth + (size_t)z * EMB * EMB;
        Bl = g_wtl + (size_t)z * EMB * EMB;
        bias = (z == 0) ? b0i : (z == 1) ? b1i : b2i;
    } else {
        Ah = g_ah; Al = g_al;
        Bh = g_wth + 3ull * EMB * EMB;
        Bl = g_wtl + 3ull * EMB * EMB;
        bias = b0i;
    }

    const uint32_t sb = smem_u32(smem);
    const int wm0 = (wid >> 2) * 64;
    const int wn0 = (wid & 3) * 32;

    float acc[4][4][4] = {};

    for (int ch = 0; ch < 16; ++ch) {
        const int k0 = ch * 64;
        __syncthreads();
        #pragma unroll
        for (int i = 0; i < 4; ++i) {
            const int idx = tid + i * 256;
            const int r = idx >> 3, c = idx & 7;
            const uint32_t sw = swz((uint32_t)(r * 128 + c * 16));
            const size_t ga = (size_t)(m0 + r) * EMB + k0 + c * 8;
            const size_t gb = (size_t)(n0 + r) * EMB + k0 + c * 8;
            *(int4*)(smem + SMEM_A_HI + sw) = *(const int4*)(Ah + ga);
            *(int4*)(smem + SMEM_A_LO + sw) = *(const int4*)(Al + ga);
            *(int4*)(smem + SMEM_B_HI + sw) = *(const int4*)(Bh + gb);
            *(int4*)(smem + SMEM_B_LO + sw) = *(const int4*)(Bl + gb);
        }
        __syncthreads();

        #pragma unroll
        for (int k16 = 0; k16 < 4; ++k16) {
            const uint32_t colB = (uint32_t)(k16 * 32 + (lid >> 4) * 16);
            uint32_t bh[4][2], bl[4][2];
            #pragma unroll
            for (int p = 0; p < 2; ++p) {
                const uint32_t off = swz((uint32_t)((wn0 + p * 16 + (lid & 15)) * 128) + colB);
                uint32_t r0, r1, r2, r3;
                ldsm_x4(r0, r1, r2, r3, sb + SMEM_B_HI + off);
                bh[2*p][0] = r0; bh[2*p][1] = r2;
                bh[2*p+1][0] = r1; bh[2*p+1][1] = r3;
                ldsm_x4(r0, r1, r2, r3, sb + SMEM_B_LO + off);
                bl[2*p][0] = r0; bl[2*p][1] = r2;
                bl[2*p+1][0] = r1; bl[2*p+1][1] = r3;
            }
            #pragma unroll
            for (int mi = 0; mi < 4; ++mi) {
                const uint32_t offA = swz((uint32_t)((wm0 + mi * 16 + (lid & 15)) * 128) + colB);
                uint32_t ahf[4], alf[4];
                ldsm_x4(ahf[0], ahf[1], ahf[2], ahf[3], sb + SMEM_A_HI + offA);
                ldsm_x4(alf[0], alf[1], alf[2], alf[3], sb + SMEM_A_LO + offA);
                #pragma unroll
                for (int ni = 0; ni < 4; ++ni) {
                    mma_bf16(acc[mi][ni], ahf, bh[ni][0], bh[ni][1]);
                    mma_bf16(acc[mi][ni], ahf, bl[ni][0], bl[ni][1]);
                    mma_bf16(acc[mi][ni], alf, bh[ni][0], bh[ni][1]);
                }
            }
        }
    }

    const int rr = lid >> 2;
    const int cc = (lid & 3) * 2;
    const float sc = (mode == 0 && z == 0) ? 0.125f : 1.0f;
    #pragma unroll
    for (int mi = 0; mi < 4; ++mi) {
        #pragma unroll
        for (int ni = 0; ni < 4; ++ni) {
            const int gcol = n0 + wn0 + ni * 8 + cc;
            const float bx = bias[gcol], by = bias[gcol + 1];
            #pragma unroll
            for (int half = 0; half < 2; ++half) {
                const int m = m0 + wm0 + mi * 16 + rr + half * 8;
                float ox = (acc[mi][ni][half * 2 + 0] + bx) * sc;
                float oy = (acc[mi][ni][half * 2 + 1] + by) * sc;
                if (mode == 0) {
                    const int bb = m >> 11, nn = m & 2047;
                    const int hh = gcol >> 6, dd = gcol & 63;
                    unsigned short hx, lx, hy, ly;
                    split2(ox, hx, lx); split2(oy, hy, ly);
                    const size_t a = ((size_t)(bb * HEADS + hh) * SEQ + nn) * HD + dd;
                    __nv_bfloat16* gh = (z == 0) ? g_qh : (z == 1) ? g_kh : g_vh;
                    __nv_bfloat16* gl = (z == 0) ? g_ql : (z == 1) ? g_kl : g_vl;
                    *(uint32_t*)&gh[a] = (uint32_t)hx | ((uint32_t)hy << 16);
                    *(uint32_t*)&gl[a] = (uint32_t)lx | ((uint32_t)ly << 16);
                } else {
                    float2 o; o.x = ox; o.y = oy;
                    *(float2*)&out0[(size_t)m * EMB + gcol] = o;
                }
            }
        }
    }
}

// ---------------------------------------------------------------------------
// HMMA flash attention. CTA: 128 q-rows x (h,b). 8 warps, warp = 16 rows.
// S = Qh*Kh + Ql*Kh + Qh*Kl ; P split in regs ; O += Ph*Vh + Pl*Vh + Ph*Vl.
// V fragments via ldmatrix.x4.trans from [token][d] layout.
// smem: Q hi/lo 32KB + 2 x (K hi/lo + V hi/lo = 64KB) = 160KB, cp.async DB.
// ---------------------------------------------------------------------------
#define AQ_HI 0
#define AQ_LO 16384
#define ABUF(b) (32768 + (b) * 65536)   // +0 Khi, +16384 Klo, +32768 Vhi, +49152 Vlo
#define ATT_SMEM (32768 + 2 * 65536)

__global__ __launch_bounds__(256) void attention_mma_kernel()
{
    extern __shared__ char smem[];
    const uint32_t sb = smem_u32(smem);
    const int tid = threadIdx.x, wid = tid >> 5, lid = tid & 31;
    const int qt = blockIdx.x, h = blockIdx.y, b = blockIdx.z;
    const size_t base = (size_t)((b * HEADS + h) * SEQ) * HD;
    const int qrow0 = qt * 128;

    // ---- group 0: Q tile + K/V tile 0 ----
    #pragma unroll
    for (int i = 0; i < 4; ++i) {
        const int idx = tid + i * 256;
        const int r = idx >> 3, c = idx & 7;
        const uint32_t sw = swz((uint32_t)(r * 128 + c * 16));
        const size_t gq = base + (size_t)(qrow0 + r) * HD + c * 8;
        cp16(sb + AQ_HI + sw, g_qh + gq);
        cp16(sb + AQ_LO + sw, g_ql + gq);
        const size_t gk = base + (size_t)r * HD + c * 8;   // tile 0
        cp16(sb + ABUF(0) +     0 + sw, g_kh + gk);
        cp16(sb + ABUF(0) + 16384 + sw, g_kl + gk);
        cp16(sb + ABUF(0) + 32768 + sw, g_vh + gk);
        cp16(sb + ABUF(0) + 49152 + sw, g_vl + gk);
    }
    CP_COMMIT();

    const int rr = lid >> 2;          // row in 8-row group
    const int cc = (lid & 3) * 2;     // col pair

    float m0r = -INFINITY, m1r = -INFINITY, l0r = 0.f, l1r = 0.f;
    float acc_o[8][4] = {};

    for (int kt = 0; kt < 16; ++kt) {
        __syncthreads();              // all warps done reading buf[(kt+1)&1] (from kt-1)
        if (kt < 15) {                // prefetch tile kt+1
            const int nb = (kt + 1) & 1;
            #pragma unroll
            for (int i = 0; i < 4; ++i) {
                const int idx = tid + i * 256;
                const int r = idx >> 3, c = idx & 7;
                const uint32_t sw = swz((uint32_t)(r * 128 + c * 16));
                const size_t gk = base + (size_t)((kt + 1) * 128 + r) * HD + c * 8;
                cp16(sb + ABUF(nb) +     0 + sw, g_kh + gk);
                cp16(sb + ABUF(nb) + 16384 + sw, g_kl + gk);
                cp16(sb + ABUF(nb) + 32768 + sw, g_vh + gk);
                cp16(sb + ABUF(nb) + 49152 + sw, g_vl + gk);
            }
            CP_COMMIT();
            CP_WAIT(1);               // tile kt ready, kt+1 may pend
        } else {
            CP_WAIT(0);
        }
        __syncthreads();              // cross-thread visibility of cp.async data

        const uint32_t KH = sb + ABUF(kt & 1);
        const uint32_t KL = KH + 16384;
        const uint32_t VH = KH + 32768;
        const uint32_t VL = KH + 49152;

        // ---- S = Q K^T (split, fp32 accum) ----
        float s[16][4];
        #pragma unroll
        for (int ni = 0; ni < 16; ++ni)
            #pragma unroll
            for (int c = 0; c < 4; ++c) s[ni][c] = 0.f;

        #pragma unroll
        for (int k16 = 0; k16 < 4; ++k16) {
            const uint32_t colB = (uint32_t)(k16 * 32 + (lid >> 4) * 16);
            const uint32_t offA = swz((uint32_t)((wid * 16 + (lid & 15)) * 128) + colB);
            uint32_t qh[4], ql[4];
            ldsm_x4(qh[0], qh[1], qh[2], qh[3], sb + AQ_HI + offA);
            ldsm_x4(ql[0], ql[1], ql[2], ql[3], sb + AQ_LO + offA);
            #pragma unroll
            for (int t = 0; t < 8; ++t) {
                const uint32_t offB = swz((uint32_t)((t * 16 + (lid & 15)) * 128) + colB);
                uint32_t r0, r1, r2, r3, u0, u1, u2, u3;
                ldsm_x4(r0, r1, r2, r3, KH + offB);
                ldsm_x4(u0, u1, u2, u3, KL + offB);
                mma_bf16(s[2*t],   qh, r0, r2);
                mma_bf16(s[2*t],   ql, r0, r2);
                mma_bf16(s[2*t],   qh, u0, u2);
                mma_bf16(s[2*t+1], qh, r1, r3);
                mma_bf16(s[2*t+1], ql, r1, r3);
                mma_bf16(s[2*t+1], qh, u1, u3);
            }
        }

        // ---- online softmax (rows rr / rr+8; reduce over quad lanes) ----
        float mx0 = -INFINITY, mx1 = -INFINITY;
        #pragma unroll
        for (int ni = 0; ni < 16; ++ni) {
            mx0 = fmaxf(mx0, fmaxf(s[ni][0], s[ni][1]));
            mx1 = fmaxf(mx1, fmaxf(s[ni][2], s[ni][3]));
        }
        #pragma unroll
        for (int msk = 1; msk <= 2; msk <<= 1) {
            mx0 = fmaxf(mx0, __shfl_xor_sync(0xffffffffu, mx0, msk));
            mx1 = fmaxf(mx1, __shfl_xor_sync(0xffffffffu, mx1, msk));
        }
        const float mn0 = fmaxf(m0r, mx0), mn1 = fmaxf(m1r, mx1);
        const float al0 = __expf(m0r - mn0), al1 = __expf(m1r - mn1);
        m0r = mn0; m1r = mn1;
        float sum0 = 0.f, sum1 = 0.f;
        #pragma unroll
        for (int ni = 0; ni < 16; ++ni) {
            s[ni][0] = __expf(s[ni][0] - mn0); sum0 += s[ni][0];
            s[ni][1] = __expf(s[ni][1] - mn0); sum0 += s[ni][1];
            s[ni][2] = __expf(s[ni][2] - mn1); sum1 += s[ni][2];
            s[ni][3] = __expf(s[ni][3] - mn1); sum1 += s[ni][3];
        }
        #pragma unroll
        for (int msk = 1; msk <= 2; msk <<= 1) {
            sum0 += __shfl_xor_sync(0xffffffffu, sum0, msk);
            sum1 += __shfl_xor_sync(0xffffffffu, sum1, msk);
        }
        l0r = l0r * al0 + sum0;
        l1r = l1r * al1 + sum1;
        #pragma unroll
        for (int di = 0; di < 8; ++di) {
            acc_o[di][0] *= al0; acc_o[di][1] *= al0;
            acc_o[di][2] *= al1; acc_o[di][3] *= al1;
        }

        // ---- O += P V (P packed from regs; V frags via ldmatrix.trans) ----
        #pragma unroll
        for (int jj = 0; jj < 8; ++jj) {
            uint32_t ph[4], pl[4];
            #pragma unroll
            for (int e = 0; e < 2; ++e) {        // e=0: ni=2jj (k0-7), e=1: ni=2jj+1 (k8-15)
                const int ni = 2 * jj + e;
                float p0 = s[ni][0], p1 = s[ni][1], p2 = s[ni][2], p3 = s[ni][3];
                __nv_bfloat16 h0 = __float2bfloat16_rn(p0), h1 = __float2bfloat16_rn(p1);
                __nv_bfloat16 h2 = __float2bfloat16_rn(p2), h3 = __float2bfloat16_rn(p3);
                ph[2*e]   = packlh(p0, p1);      // rows rr,  k pair (uses cvt of p directly)
                ph[2*e+1] = packlh(p2, p3);      // rows rr+8
                pl[2*e]   = packlh(p0 - __bfloat162float(h0), p1 - __bfloat162float(h1));
                pl[2*e+1] = packlh(p2 - __bfloat162float(h2), p3 - __bfloat162float(h3));
            }
            #pragma unroll
            for (int dt = 0; dt < 4; ++dt) {     // d-tile pairs
                const uint32_t va = swz((uint32_t)((jj * 16 + (lid & 15)) * 128 +
                                                   dt * 32 + (lid >> 4) * 16));
                uint32_t v0, v1, v2, v3, w0, w1, w2, w3;
                ldsm_x4_t(v0, v1, v2, v3, VH + va);
                ldsm_x4_t(w0, w1, w2, w3, VL + va);
                mma_bf16(acc_o[2*dt],   ph, v0, v1);
                mma_bf16(acc_o[2*dt],   pl, v0, v1);
                mma_bf16(acc_o[2*dt],   ph, w0, w1);
                mma_bf16(acc_o[2*dt+1], ph, v2, v3);
                mma_bf16(acc_o[2*dt+1], pl, v2, v3);
                mma_bf16(acc_o[2*dt+1], ph, w2, w3);
            }
        }
    }

    // ---- epilogue: normalize, split, write g_ah/g_al [b, i, h*64+d] ----
    const float inv0 = 1.0f / l0r, inv1 = 1.0f / l1r;
    const int i0 = qrow0 + wid * 16 + rr;
    #pragma unroll
    for (int di = 0; di < 8; ++di) {
        const int col = h * HD + di * 8 + cc;
        {
            float ox = acc_o[di][0] * inv0, oy = acc_o[di][1] * inv0;
            unsigned short hx, lx, hy, ly;
            split2(ox, hx, lx); split2(oy, hy, ly);
            const size_t a = ((size_t)(b * SEQ) + i0) * EMB + col;
            *(uint32_t*)&g_ah[a] = (uint32_t)hx | ((uint32_t)hy << 16);
            *(uint32_t*)&g_al[a] = (uint32_t)lx | ((uint32_t)ly << 16);
        }
        {
            float ox = acc_o[di][2] * inv1, oy = acc_o[di][3] * inv1;
            unsigned short hx, lx, hy, ly;
            split2(ox, hx, lx); split2(oy, hy, ly);
            const size_t a = ((size_t)(b * SEQ) + i0 + 8) * EMB + col;
            *(uint32_t*)&g_ah[a] = (uint32_t)hx | ((uint32_t)hy << 16);
            *(uint32_t*)&g_al[a] = (uint32_t)lx | ((uint32_t)ly << 16);
        }
    }
}

// ---------------------------------------------------------------------------
// Dispatch (robust size-class mapping, proven R4-R7)
// ---------------------------------------------------------------------------
extern "C" void kernel_launch(void* const* d_in, const int* in_sizes, int n_in,
                              void* d_out, int out_size)
{
    (void)out_size;

    long long scale = 1;
    for (int i = 0; i < n_in; ++i)
        if ((long long)in_sizes[i] == 16777216LL) { scale = 4; break; }

    const float* x  = (const float*)d_in[0];
    const float* Wenc[4] = { (const float*)d_in[1], (const float*)d_in[3],
                             (const float*)d_in[5], (const float*)d_in[7] };
    const float* benc[4] = { (const float*)d_in[2], (const float*)d_in[4],
                             (const float*)d_in[6], (const float*)d_in[8] };
    int wIdx[4] = { 1, 3, 5, 7 };
    int nw = 0, nb = 0;

    for (int i = 0; i < n_in; ++i) {
        long long elems = (long long)in_sizes[i] / scale;
        if (elems == (long long)BATCH * SEQ * EMB) {
            x = (const float*)d_in[i];
        } else if (elems == (long long)EMB * EMB) {
            if (nw < 4) { wIdx[nw] = i; Wenc[nw] = (const float*)d_in[i]; }
            ++nw;
        } else if (elems == (long long)EMB) {
            if (nb < 4) { benc[nb] = (const float*)d_in[i]; }
            ++nb;
        }
    }

    bool sortedLayout = false;
    if (nw == 4 && nb == 4)
        sortedLayout = (wIdx[1] == wIdx[0] + 1) &&
                       (wIdx[2] == wIdx[1] + 1) &&
                       (wIdx[3] == wIdx[2] + 1);

    const float *Wq, *Wk, *Wv, *Wo, *bq, *bk, *bv, *bo;
    if (sortedLayout) {
        Wk = Wenc[0]; Wo = Wenc[1]; Wq = Wenc[2]; Wv = Wenc[3];
        bk = benc[0]; bo = benc[1]; bq = benc[2]; bv = benc[3];
    } else {
        Wq = Wenc[0]; Wk = Wenc[1]; Wv = Wenc[2]; Wo = Wenc[3];
        bq = benc[0]; bk = benc[1]; bv = benc[2]; bo = benc[3];
    }

    float* out = (float*)d_out;

    cudaFuncSetAttribute(mma_gemm_kernel,
                         cudaFuncAttributeMaxDynamicSharedMemorySize, SMEM_DYN);
    cudaFuncSetAttribute(attention_mma_kernel,
                         cudaFuncAttributeMaxDynamicSharedMemorySize, ATT_SMEM);

    cvt_x_kernel<<<MROWS * EMB / 1024, 256>>>(x);
    transpose_cvt_kernel<<<dim3(EMB / 32, EMB / 32, 4), 256>>>(Wq, Wk, Wv, Wo);

    // QKV projections -> split-bf16 q/k/v (Q pre-scaled 1/8)
    mma_gemm_kernel<<<dim3(EMB / 128, MROWS / 128, 3), 256, SMEM_DYN>>>(
        bq, bk, bv, nullptr, 0);

    // HMMA flash attention -> split-bf16 attn output
    attention_mma_kernel<<<dim3(SEQ / 128, HEADS, BATCH), 256, ATT_SMEM>>>();

    // output projection -> fp32 out
    mma_gemm_kernel<<<dim3(EMB / 128, MROWS / 128, 1), 256, SMEM_DYN>>>(
        bo, bo, bo, out, 1);
}

// round 9
// speedup vs baseline: 2.9973x; 1.1038x over previous
#include <cuda_runtime.h>
#include <cuda_bf16.h>
#include <math.h>
#include <stdint.h>

#define BATCH 2
#define SEQ   2048
#define EMB   1024
#define HEADS 16
#define HD    64
#define MROWS (BATCH*SEQ)   // 4096

// ---------------------------------------------------------------------------
// Scratch (__device__ globals; allocation-free rule)
// ---------------------------------------------------------------------------
__device__ __align__(16) __nv_bfloat16 g_xh[MROWS*EMB];
__device__ __align__(16) __nv_bfloat16 g_xl[MROWS*EMB];
__device__ __align__(16) __nv_bfloat16 g_wth[4u*EMB*EMB];   // W^T hi: q,k,v,o
__device__ __align__(16) __nv_bfloat16 g_wtl[4u*EMB*EMB];   // W^T lo
__device__ __align__(16) __nv_bfloat16 g_qh[BATCH*HEADS*SEQ*HD];  // pre-scaled 1/8
__device__ __align__(16) __nv_bfloat16 g_ql[BATCH*HEADS*SEQ*HD];
__device__ __align__(16) __nv_bfloat16 g_kh[BATCH*HEADS*SEQ*HD];
__device__ __align__(16) __nv_bfloat16 g_kl[BATCH*HEADS*SEQ*HD];
__device__ __align__(16) __nv_bfloat16 g_vh[BATCH*HEADS*SEQ*HD];
__device__ __align__(16) __nv_bfloat16 g_vl[BATCH*HEADS*SEQ*HD];
__device__ __align__(16) __nv_bfloat16 g_ah[MROWS*EMB];     // attn out hi
__device__ __align__(16) __nv_bfloat16 g_al[MROWS*EMB];     // attn out lo

// ---------------------------------------------------------------------------
// PTX helpers (sm_80+ subset: assembles for compute_100)
// ---------------------------------------------------------------------------
__device__ __forceinline__ uint32_t smem_u32(const void* p) {
    uint32_t a;
    asm("{ .reg .u64 t; cvta.to.shared.u64 t, %1; cvt.u32.u64 %0, t; }"
        : "=r"(a) : "l"(p));
    return a;
}
__device__ __forceinline__ void ldsm_x4(uint32_t& r0, uint32_t& r1,
                                        uint32_t& r2, uint32_t& r3, uint32_t a) {
    asm volatile("ldmatrix.sync.aligned.m8n8.x4.shared.b16 {%0,%1,%2,%3}, [%4];"
                 : "=r"(r0), "=r"(r1), "=r"(r2), "=r"(r3) : "r"(a));
}
__device__ __forceinline__ void ldsm_x4_t(uint32_t& r0, uint32_t& r1,
                                          uint32_t& r2, uint32_t& r3, uint32_t a) {
    asm volatile("ldmatrix.sync.aligned.m8n8.x4.trans.shared.b16 {%0,%1,%2,%3}, [%4];"
                 : "=r"(r0), "=r"(r1), "=r"(r2), "=r"(r3) : "r"(a));
}
__device__ __forceinline__ void mma_bf16(float* d, const uint32_t* a,
                                         uint32_t b0, uint32_t b1) {
    asm volatile("mma.sync.aligned.m16n8k16.row.col.f32.bf16.bf16.f32 "
                 "{%0,%1,%2,%3}, {%4,%5,%6,%7}, {%8,%9}, {%0,%1,%2,%3};"
                 : "+f"(d[0]), "+f"(d[1]), "+f"(d[2]), "+f"(d[3])
                 : "r"(a[0]), "r"(a[1]), "r"(a[2]), "r"(a[3]), "r"(b0), "r"(b1));
}
__device__ __forceinline__ void cp16(uint32_t dst, const void* src) {
    asm volatile("cp.async.cg.shared.global [%0], [%1], 16;"
                 :: "r"(dst), "l"(src) : "memory");
}
#define CP_COMMIT() asm volatile("cp.async.commit_group;" ::: "memory")
#define CP_WAIT(N)  asm volatile("cp.async.wait_group %0;" :: "n"(N) : "memory")

__device__ __forceinline__ uint32_t swz(uint32_t o) { return o ^ ((o >> 3) & 0x70); }

__device__ __forceinline__ void split2(float a, unsigned short& h, unsigned short& l) {
    __nv_bfloat16 hb = __float2bfloat16_rn(a);
    __nv_bfloat16 lb = __float2bfloat16_rn(a - __bfloat162float(hb));
    h = __bfloat16_as_ushort(hb);
    l = __bfloat16_as_ushort(lb);
}
__device__ __forceinline__ uint32_t packlh(float lo, float hi) {
    uint32_t r;
    asm("cvt.rn.bf16x2.f32 %0, %1, %2;" : "=r"(r) : "f"(hi), "f"(lo));
    return r;
}

// ---------------------------------------------------------------------------
// conversion kernels
// ---------------------------------------------------------------------------
__global__ __launch_bounds__(256) void cvt_x_kernel(const float* __restrict__ src) {
    int i = blockIdx.x * 256 + threadIdx.x;
    float4 v = ((const float4*)src)[i];
    ushort4 h, l;
    split2(v.x, h.x, l.x); split2(v.y, h.y, l.y);
    split2(v.z, h.z, l.z); split2(v.w, h.w, l.w);
    ((ushort4*)g_xh)[i] = h;
    ((ushort4*)g_xl)[i] = l;
}
__global__ __launch_bounds__(256) void transpose_cvt_kernel(
    const float* __restrict__ Wq, const float* __restrict__ Wk,
    const float* __restrict__ Wv, const float* __restrict__ Wo)
{
    const float* __restrict__ src =
        (blockIdx.z == 0) ? Wq : (blockIdx.z == 1) ? Wk : (blockIdx.z == 2) ? Wv : Wo;
    __shared__ float t[32][33];
    const int tx = threadIdx.x & 31, ty = threadIdx.x >> 5;
    const int k0 = blockIdx.x * 32, n0 = blockIdx.y * 32;
    #pragma unroll
    for (int i = 0; i < 4; ++i) {
        int r = ty + i * 8;
        t[r][tx] = src[(size_t)(k0 + r) * EMB + n0 + tx];
    }
    __syncthreads();
    const size_t base = (size_t)blockIdx.z * EMB * EMB;
    #pragma unroll
    for (int i = 0; i < 4; ++i) {
        int r = ty + i * 8;
        float a = t[tx][r];
        unsigned short h, l;
        split2(a, h, l);
        size_t o = base + (size_t)(n0 + r) * EMB + k0 + tx;
        g_wth[o] = __ushort_as_bfloat16(h);
        g_wtl[o] = __ushort_as_bfloat16(l);
    }
}

// ---------------------------------------------------------------------------
// split-bf16 HMMA GEMM, 2-stage cp.async pipeline (R9).
// CTA 128x128, K-chunk 64, 8 warps 2x4, warp 64x32.
// mode 0: QKV -> split-bf16 q/k/v [b,h,token,d] (Q pre-scaled 1/8)
// mode 1: out projection -> fp32 row-major (+bias)
// smem: 2 stages x 4 arrays x 16KB = 128KB.
// ---------------------------------------------------------------------------
#define GSTAGE 65536
#define GA_HI  0
#define GA_LO  16384
#define GB_HI  32768
#define GB_LO  49152
#define SMEM_DYN (2 * GSTAGE)

__global__ __launch_bounds__(256, 1) void mma_gemm_kernel(
    const float* __restrict__ b0i, const float* __restrict__ b1i,
    const float* __restrict__ b2i, float* __restrict__ out0, int mode)
{
    extern __shared__ char smem[];
    const int tid = threadIdx.x, wid = tid >> 5, lid = tid & 31;
    const int n0 = blockIdx.x * 128, m0 = blockIdx.y * 128;
    const int z = blockIdx.z;

    const __nv_bfloat16 *Ah, *Al, *Bh, *Bl;
    const float* bias;
    if (mode == 0) {
        Ah = g_xh; Al = g_xl;
        Bh = g_wth + (size_t)z * EMB * EMB;
        Bl = g_wtl + (size_t)z * EMB * EMB;
        bias = (z == 0) ? b0i : (z == 1) ? b1i : b2i;
    } else {
        Ah = g_ah; Al = g_al;
        Bh = g_wth + 3ull * EMB * EMB;
        Bl = g_wtl + 3ull * EMB * EMB;
        bias = b0i;
    }

    const uint32_t sb = smem_u32(smem);
    const int wm0 = (wid >> 2) * 64;
    const int wn0 = (wid & 3) * 32;

    // per-thread load role (8 cp16s per stage)
    const int lr = tid >> 3;              // row 0..31 base (x4 rows via i)
    const int lc = tid & 7;               // 16B chunk 0..7

    // prefetch chunk 0 into stage 0
    {
        #pragma unroll
        for (int i = 0; i < 4; ++i) {
            const int r = lr + i * 32;
            const uint32_t sw = swz((uint32_t)(r * 128 + lc * 16));
            const size_t ga = (size_t)(m0 + r) * EMB + lc * 8;
            const size_t gb = (size_t)(n0 + r) * EMB + lc * 8;
            cp16(sb + GA_HI + sw, Ah + ga);
            cp16(sb + GA_LO + sw, Al + ga);
            cp16(sb + GB_HI + sw, Bh + gb);
            cp16(sb + GB_LO + sw, Bl + gb);
        }
        CP_COMMIT();
    }

    float acc[4][4][4] = {};

    for (int ch = 0; ch < 16; ++ch) {
        if (ch < 15) {
            const uint32_t st = sb + ((ch + 1) & 1) * GSTAGE;
            const int k0n = (ch + 1) * 64;
            #pragma unroll
            for (int i = 0; i < 4; ++i) {
                const int r = lr + i * 32;
                const uint32_t sw = swz((uint32_t)(r * 128 + lc * 16));
                const size_t ga = (size_t)(m0 + r) * EMB + k0n + lc * 8;
                const size_t gb = (size_t)(n0 + r) * EMB + k0n + lc * 8;
                cp16(st + GA_HI + sw, Ah + ga);
                cp16(st + GA_LO + sw, Al + ga);
                cp16(st + GB_HI + sw, Bh + gb);
                cp16(st + GB_LO + sw, Bl + gb);
            }
            CP_COMMIT();
            CP_WAIT(1);
        } else {
            CP_WAIT(0);
        }
        __syncthreads();

        const uint32_t cs = sb + (ch & 1) * GSTAGE;
        #pragma unroll
        for (int k16 = 0; k16 < 4; ++k16) {
            const uint32_t colB = (uint32_t)(k16 * 32 + (lid >> 4) * 16);
            uint32_t bh[4][2], bl[4][2];
            #pragma unroll
            for (int p = 0; p < 2; ++p) {
                const uint32_t off = swz((uint32_t)((wn0 + p * 16 + (lid & 15)) * 128) + colB);
                uint32_t r0, r1, r2, r3;
                ldsm_x4(r0, r1, r2, r3, cs + GB_HI + off);
                bh[2*p][0] = r0; bh[2*p][1] = r2;
                bh[2*p+1][0] = r1; bh[2*p+1][1] = r3;
                ldsm_x4(r0, r1, r2, r3, cs + GB_LO + off);
                bl[2*p][0] = r0; bl[2*p][1] = r2;
                bl[2*p+1][0] = r1; bl[2*p+1][1] = r3;
            }
            #pragma unroll
            for (int mi = 0; mi < 4; ++mi) {
                const uint32_t offA = swz((uint32_t)((wm0 + mi * 16 + (lid & 15)) * 128) + colB);
                uint32_t ahf[4], alf[4];
                ldsm_x4(ahf[0], ahf[1], ahf[2], ahf[3], cs + GA_HI + offA);
                ldsm_x4(alf[0], alf[1], alf[2], alf[3], cs + GA_LO + offA);
                #pragma unroll
                for (int ni = 0; ni < 4; ++ni) {
                    mma_bf16(acc[mi][ni], ahf, bh[ni][0], bh[ni][1]);
                    mma_bf16(acc[mi][ni], ahf, bl[ni][0], bl[ni][1]);
                    mma_bf16(acc[mi][ni], alf, bh[ni][0], bh[ni][1]);
                }
            }
        }
        __syncthreads();
    }

    const int rr = lid >> 2;
    const int cc = (lid & 3) * 2;
    const float sc = (mode == 0 && z == 0) ? 0.125f : 1.0f;
    #pragma unroll
    for (int mi = 0; mi < 4; ++mi) {
        #pragma unroll
        for (int ni = 0; ni < 4; ++ni) {
            const int gcol = n0 + wn0 + ni * 8 + cc;
            const float bx = bias[gcol], by = bias[gcol + 1];
            #pragma unroll
            for (int half = 0; half < 2; ++half) {
                const int m = m0 + wm0 + mi * 16 + rr + half * 8;
                float ox = (acc[mi][ni][half * 2 + 0] + bx) * sc;
                float oy = (acc[mi][ni][half * 2 + 1] + by) * sc;
                if (mode == 0) {
                    const int bb = m >> 11, nn = m & 2047;
                    const int hh = gcol >> 6, dd = gcol & 63;
                    unsigned short hx, lx, hy, ly;
                    split2(ox, hx, lx); split2(oy, hy, ly);
                    const size_t a = ((size_t)(bb * HEADS + hh) * SEQ + nn) * HD + dd;
                    __nv_bfloat16* gh = (z == 0) ? g_qh : (z == 1) ? g_kh : g_vh;
                    __nv_bfloat16* gl = (z == 0) ? g_ql : (z == 1) ? g_kl : g_vl;
                    *(uint32_t*)&gh[a] = (uint32_t)hx | ((uint32_t)hy << 16);
                    *(uint32_t*)&gl[a] = (uint32_t)lx | ((uint32_t)ly << 16);
                } else {
                    float2 o; o.x = ox; o.y = oy;
                    *(float2*)&out0[(size_t)m * EMB + gcol] = o;
                }
            }
        }
    }
}

// ---------------------------------------------------------------------------
// HMMA flash attention (unchanged from R8 — verified)
// ---------------------------------------------------------------------------
#define AQ_HI 0
#define AQ_LO 16384
#define ABUF(b) (32768 + (b) * 65536)
#define ATT_SMEM (32768 + 2 * 65536)

__global__ __launch_bounds__(256) void attention_mma_kernel()
{
    extern __shared__ char smem[];
    const uint32_t sb = smem_u32(smem);
    const int tid = threadIdx.x, wid = tid >> 5, lid = tid & 31;
    const int qt = blockIdx.x, h = blockIdx.y, b = blockIdx.z;
    const size_t base = (size_t)((b * HEADS + h) * SEQ) * HD;
    const int qrow0 = qt * 128;

    #pragma unroll
    for (int i = 0; i < 4; ++i) {
        const int idx = tid + i * 256;
        const int r = idx >> 3, c = idx & 7;
        const uint32_t sw = swz((uint32_t)(r * 128 + c * 16));
        const size_t gq = base + (size_t)(qrow0 + r) * HD + c * 8;
        cp16(sb + AQ_HI + sw, g_qh + gq);
        cp16(sb + AQ_LO + sw, g_ql + gq);
        const size_t gk = base + (size_t)r * HD + c * 8;
        cp16(sb + ABUF(0) +     0 + sw, g_kh + gk);
        cp16(sb + ABUF(0) + 16384 + sw, g_kl + gk);
        cp16(sb + ABUF(0) + 32768 + sw, g_vh + gk);
        cp16(sb + ABUF(0) + 49152 + sw, g_vl + gk);
    }
    CP_COMMIT();

    const int rr = lid >> 2;
    const int cc = (lid & 3) * 2;

    float m0r = -INFINITY, m1r = -INFINITY, l0r = 0.f, l1r = 0.f;
    float acc_o[8][4] = {};

    for (int kt = 0; kt < 16; ++kt) {
        __syncthreads();
        if (kt < 15) {
            const int nb = (kt + 1) & 1;
            #pragma unroll
            for (int i = 0; i < 4; ++i) {
                const int idx = tid + i * 256;
                const int r = idx >> 3, c = idx & 7;
                const uint32_t sw = swz((uint32_t)(r * 128 + c * 16));
                const size_t gk = base + (size_t)((kt + 1) * 128 + r) * HD + c * 8;
                cp16(sb + ABUF(nb) +     0 + sw, g_kh + gk);
                cp16(sb + ABUF(nb) + 16384 + sw, g_kl + gk);
                cp16(sb + ABUF(nb) + 32768 + sw, g_vh + gk);
                cp16(sb + ABUF(nb) + 49152 + sw, g_vl + gk);
            }
            CP_COMMIT();
            CP_WAIT(1);
        } else {
            CP_WAIT(0);
        }
        __syncthreads();

        const uint32_t KH = sb + ABUF(kt & 1);
        const uint32_t KL = KH + 16384;
        const uint32_t VH = KH + 32768;
        const uint32_t VL = KH + 49152;

        float s[16][4];
        #pragma unroll
        for (int ni = 0; ni < 16; ++ni)
            #pragma unroll
            for (int c = 0; c < 4; ++c) s[ni][c] = 0.f;

        #pragma unroll
        for (int k16 = 0; k16 < 4; ++k16) {
            const uint32_t colB = (uint32_t)(k16 * 32 + (lid >> 4) * 16);
            const uint32_t offA = swz((uint32_t)((wid * 16 + (lid & 15)) * 128) + colB);
            uint32_t qh[4], ql[4];
            ldsm_x4(qh[0], qh[1], qh[2], qh[3], sb + AQ_HI + offA);
            ldsm_x4(ql[0], ql[1], ql[2], ql[3], sb + AQ_LO + offA);
            #pragma unroll
            for (int t = 0; t < 8; ++t) {
                const uint32_t offB = swz((uint32_t)((t * 16 + (lid & 15)) * 128) + colB);
                uint32_t r0, r1, r2, r3, u0, u1, u2, u3;
                ldsm_x4(r0, r1, r2, r3, KH + offB);
                ldsm_x4(u0, u1, u2, u3, KL + offB);
                mma_bf16(s[2*t],   qh, r0, r2);
                mma_bf16(s[2*t],   ql, r0, r2);
                mma_bf16(s[2*t],   qh, u0, u2);
                mma_bf16(s[2*t+1], qh, r1, r3);
                mma_bf16(s[2*t+1], ql, r1, r3);
                mma_bf16(s[2*t+1], qh, u1, u3);
            }
        }

        float mx0 = -INFINITY, mx1 = -INFINITY;
        #pragma unroll
        for (int ni = 0; ni < 16; ++ni) {
            mx0 = fmaxf(mx0, fmaxf(s[ni][0], s[ni][1]));
            mx1 = fmaxf(mx1, fmaxf(s[ni][2], s[ni][3]));
        }
        #pragma unroll
        for (int msk = 1; msk <= 2; msk <<= 1) {
            mx0 = fmaxf(mx0, __shfl_xor_sync(0xffffffffu, mx0, msk));
            mx1 = fmaxf(mx1, __shfl_xor_sync(0xffffffffu, mx1, msk));
        }
        const float mn0 = fmaxf(m0r, mx0), mn1 = fmaxf(m1r, mx1);
        const float al0 = __expf(m0r - mn0), al1 = __expf(m1r - mn1);
        m0r = mn0; m1r = mn1;
        float sum0 = 0.f, sum1 = 0.f;
        #pragma unroll
        for (int ni = 0; ni < 16; ++ni) {
            s[ni][0] = __expf(s[ni][0] - mn0); sum0 += s[ni][0];
            s[ni][1] = __expf(s[ni][1] - mn0); sum0 += s[ni][1];
            s[ni][2] = __expf(s[ni][2] - mn1); sum1 += s[ni][2];
            s[ni][3] = __expf(s[ni][3] - mn1); sum1 += s[ni][3];
        }
        #pragma unroll
        for (int msk = 1; msk <= 2; msk <<= 1) {
            sum0 += __shfl_xor_sync(0xffffffffu, sum0, msk);
            sum1 += __shfl_xor_sync(0xffffffffu, sum1, msk);
        }
        l0r = l0r * al0 + sum0;
        l1r = l1r * al1 + sum1;
        #pragma unroll
        for (int di = 0; di < 8; ++di) {
            acc_o[di][0] *= al0; acc_o[di][1] *= al0;
            acc_o[di][2] *= al1; acc_o[di][3] *= al1;
        }

        #pragma unroll
        for (int jj = 0; jj < 8; ++jj) {
            uint32_t ph[4], pl[4];
            #pragma unroll
            for (int e = 0; e < 2; ++e) {
                const int ni = 2 * jj + e;
                float p0 = s[ni][0], p1 = s[ni][1], p2 = s[ni][2], p3 = s[ni][3];
                __nv_bfloat16 h0 = __float2bfloat16_rn(p0), h1 = __float2bfloat16_rn(p1);
                __nv_bfloat16 h2 = __float2bfloat16_rn(p2), h3 = __float2bfloat16_rn(p3);
                ph[2*e]   = packlh(p0, p1);
                ph[2*e+1] = packlh(p2, p3);
                pl[2*e]   = packlh(p0 - __bfloat162float(h0), p1 - __bfloat162float(h1));
                pl[2*e+1] = packlh(p2 - __bfloat162float(h2), p3 - __bfloat162float(h3));
            }
            #pragma unroll
            for (int dt = 0; dt < 4; ++dt) {
                const uint32_t va = swz((uint32_t)((jj * 16 + (lid & 15)) * 128 +
                                                   dt * 32 + (lid >> 4) * 16));
                uint32_t v0, v1, v2, v3, w0, w1, w2, w3;
                ldsm_x4_t(v0, v1, v2, v3, VH + va);
                ldsm_x4_t(w0, w1, w2, w3, VL + va);
                mma_bf16(acc_o[2*dt],   ph, v0, v1);
                mma_bf16(acc_o[2*dt],   pl, v0, v1);
                mma_bf16(acc_o[2*dt],   ph, w0, w1);
                mma_bf16(acc_o[2*dt+1], ph, v2, v3);
                mma_bf16(acc_o[2*dt+1], pl, v2, v3);
                mma_bf16(acc_o[2*dt+1], ph, w2, w3);
            }
        }
    }

    const float inv0 = 1.0f / l0r, inv1 = 1.0f / l1r;
    const int i0 = qrow0 + wid * 16 + rr;
    #pragma unroll
    for (int di = 0; di < 8; ++di) {
        const int col = h * HD + di * 8 + cc;
        {
            float ox = acc_o[di][0] * inv0, oy = acc_o[di][1] * inv0;
            unsigned short hx, lx, hy, ly;
            split2(ox, hx, lx); split2(oy, hy, ly);
            const size_t a = ((size_t)(b * SEQ) + i0) * EMB + col;
            *(uint32_t*)&g_ah[a] = (uint32_t)hx | ((uint32_t)hy << 16);
            *(uint32_t*)&g_al[a] = (uint32_t)lx | ((uint32_t)ly << 16);
        }
        {
            float ox = acc_o[di][2] * inv1, oy = acc_o[di][3] * inv1;
            unsigned short hx, lx, hy, ly;
            split2(ox, hx, lx); split2(oy, hy, ly);
            const size_t a = ((size_t)(b * SEQ) + i0 + 8) * EMB + col;
            *(uint32_t*)&g_ah[a] = (uint32_t)hx | ((uint32_t)hy << 16);
            *(uint32_t*)&g_al[a] = (uint32_t)lx | ((uint32_t)ly << 16);
        }
    }
}

// ---------------------------------------------------------------------------
// Dispatch (robust size-class mapping, proven R4-R8)
// ---------------------------------------------------------------------------
extern "C" void kernel_launch(void* const* d_in, const int* in_sizes, int n_in,
                              void* d_out, int out_size)
{
    (void)out_size;

    long long scale = 1;
    for (int i = 0; i < n_in; ++i)
        if ((long long)in_sizes[i] == 16777216LL) { scale = 4; break; }

    const float* x  = (const float*)d_in[0];
    const float* Wenc[4] = { (const float*)d_in[1], (const float*)d_in[3],
                             (const float*)d_in[5], (const float*)d_in[7] };
    const float* benc[4] = { (const float*)d_in[2], (const float*)d_in[4],
                             (const float*)d_in[6], (const float*)d_in[8] };
    int wIdx[4] = { 1, 3, 5, 7 };
    int nw = 0, nb = 0;

    for (int i = 0; i < n_in; ++i) {
        long long elems = (long long)in_sizes[i] / scale;
        if (elems == (long long)BATCH * SEQ * EMB) {
            x = (const float*)d_in[i];
        } else if (elems == (long long)EMB * EMB) {
            if (nw < 4) { wIdx[nw] = i; Wenc[nw] = (const float*)d_in[i]; }
            ++nw;
        } else if (elems == (long long)EMB) {
            if (nb < 4) { benc[nb] = (const float*)d_in[i]; }
            ++nb;
        }
    }

    bool sortedLayout = false;
    if (nw == 4 && nb == 4)
        sortedLayout = (wIdx[1] == wIdx[0] + 1) &&
                       (wIdx[2] == wIdx[1] + 1) &&
                       (wIdx[3] == wIdx[2] + 1);

    const float *Wq, *Wk, *Wv, *Wo, *bq, *bk, *bv, *bo;
    if (sortedLayout) {
        Wk = Wenc[0]; Wo = Wenc[1]; Wq = Wenc[2]; Wv = Wenc[3];
        bk = benc[0]; bo = benc[1]; bq = benc[2]; bv = benc[3];
    } else {
        Wq = Wenc[0]; Wk = Wenc[1]; Wv = Wenc[2]; Wo = Wenc[3];
        bq = benc[0]; bk = benc[1]; bv = benc[2]; bo = benc[3];
    }

    float* out = (float*)d_out;

    cudaFuncSetAttribute(mma_gemm_kernel,
                         cudaFuncAttributeMaxDynamicSharedMemorySize, SMEM_DYN);
    cudaFuncSetAttribute(attention_mma_kernel,
                         cudaFuncAttributeMaxDynamicSharedMemorySize, ATT_SMEM);

    cvt_x_kernel<<<MROWS * EMB / 1024, 256>>>(x);
    transpose_cvt_kernel<<<dim3(EMB / 32, EMB / 32, 4), 256>>>(Wq, Wk, Wv, Wo);

    mma_gemm_kernel<<<dim3(EMB / 128, MROWS / 128, 3), 256, SMEM_DYN>>>(
        bq, bk, bv, nullptr, 0);

    attention_mma_kernel<<<dim3(SEQ / 128, HEADS, BATCH), 256, ATT_SMEM>>>();

    mma_gemm_kernel<<<dim3(EMB / 128, MROWS / 128, 1), 256, SMEM_DYN>>>(
        bo, bo, bo, out, 1);
}

// round 10
// speedup vs baseline: 3.0129x; 1.0052x over previous
#include <cuda_runtime.h>
#include <cuda_bf16.h>
#include <math.h>
#include <stdint.h>

#define BATCH 2
#define SEQ   2048
#define EMB   1024
#define HEADS 16
#define HD    64
#define MROWS (BATCH*SEQ)   // 4096

// ---------------------------------------------------------------------------
// Scratch (__device__ globals; allocation-free rule)
// ---------------------------------------------------------------------------
__device__ __align__(16) __nv_bfloat16 g_xh[MROWS*EMB];
__device__ __align__(16) __nv_bfloat16 g_xl[MROWS*EMB];
__device__ __align__(16) __nv_bfloat16 g_wth[4u*EMB*EMB];   // W^T hi: q,k,v,o
__device__ __align__(16) __nv_bfloat16 g_wtl[4u*EMB*EMB];   // W^T lo
__device__ __align__(16) __nv_bfloat16 g_qh[BATCH*HEADS*SEQ*HD];  // pre-scaled 1/8
__device__ __align__(16) __nv_bfloat16 g_ql[BATCH*HEADS*SEQ*HD];
__device__ __align__(16) __nv_bfloat16 g_kh[BATCH*HEADS*SEQ*HD];
__device__ __align__(16) __nv_bfloat16 g_kl[BATCH*HEADS*SEQ*HD];
__device__ __align__(16) __nv_bfloat16 g_vh[BATCH*HEADS*SEQ*HD];
__device__ __align__(16) __nv_bfloat16 g_vl[BATCH*HEADS*SEQ*HD];
__device__ __align__(16) __nv_bfloat16 g_ah[MROWS*EMB];     // attn out hi
__device__ __align__(16) __nv_bfloat16 g_al[MROWS*EMB];     // attn out lo

// ---------------------------------------------------------------------------
// PTX helpers (sm_80+ subset: assembles for compute_100)
// ---------------------------------------------------------------------------
__device__ __forceinline__ uint32_t smem_u32(const void* p) {
    uint32_t a;
    asm("{ .reg .u64 t; cvta.to.shared.u64 t, %1; cvt.u32.u64 %0, t; }"
        : "=r"(a) : "l"(p));
    return a;
}
__device__ __forceinline__ void ldsm_x4(uint32_t& r0, uint32_t& r1,
                                        uint32_t& r2, uint32_t& r3, uint32_t a) {
    asm volatile("ldmatrix.sync.aligned.m8n8.x4.shared.b16 {%0,%1,%2,%3}, [%4];"
                 : "=r"(r0), "=r"(r1), "=r"(r2), "=r"(r3) : "r"(a));
}
__device__ __forceinline__ void ldsm_x4_t(uint32_t& r0, uint32_t& r1,
                                          uint32_t& r2, uint32_t& r3, uint32_t a) {
    asm volatile("ldmatrix.sync.aligned.m8n8.x4.trans.shared.b16 {%0,%1,%2,%3}, [%4];"
                 : "=r"(r0), "=r"(r1), "=r"(r2), "=r"(r3) : "r"(a));
}
__device__ __forceinline__ void mma_bf16(float* d, const uint32_t* a,
                                         uint32_t b0, uint32_t b1) {
    asm volatile("mma.sync.aligned.m16n8k16.row.col.f32.bf16.bf16.f32 "
                 "{%0,%1,%2,%3}, {%4,%5,%6,%7}, {%8,%9}, {%0,%1,%2,%3};"
                 : "+f"(d[0]), "+f"(d[1]), "+f"(d[2]), "+f"(d[3])
                 : "r"(a[0]), "r"(a[1]), "r"(a[2]), "r"(a[3]), "r"(b0), "r"(b1));
}
__device__ __forceinline__ void cp16(uint32_t dst, const void* src) {
    asm volatile("cp.async.cg.shared.global [%0], [%1], 16;"
                 :: "r"(dst), "l"(src) : "memory");
}
#define CP_COMMIT() asm volatile("cp.async.commit_group;" ::: "memory")
#define CP_WAIT(N)  asm volatile("cp.async.wait_group %0;" :: "n"(N) : "memory")

__device__ __forceinline__ uint32_t swz(uint32_t o) { return o ^ ((o >> 3) & 0x70); }

__device__ __forceinline__ void split2(float a, unsigned short& h, unsigned short& l) {
    __nv_bfloat16 hb = __float2bfloat16_rn(a);
    __nv_bfloat16 lb = __float2bfloat16_rn(a - __bfloat162float(hb));
    h = __bfloat16_as_ushort(hb);
    l = __bfloat16_as_ushort(lb);
}
__device__ __forceinline__ uint32_t packlh(float lo, float hi) {
    uint32_t r;
    asm("cvt.rn.bf16x2.f32 %0, %1, %2;" : "=r"(r) : "f"(hi), "f"(lo));
    return r;
}

// ---------------------------------------------------------------------------
// conversion kernels
// ---------------------------------------------------------------------------
__global__ __launch_bounds__(256) void cvt_x_kernel(const float* __restrict__ src) {
    int i = blockIdx.x * 256 + threadIdx.x;
    float4 v = ((const float4*)src)[i];
    ushort4 h, l;
    split2(v.x, h.x, l.x); split2(v.y, h.y, l.y);
    split2(v.z, h.z, l.z); split2(v.w, h.w, l.w);
    ((ushort4*)g_xh)[i] = h;
    ((ushort4*)g_xl)[i] = l;
}
__global__ __launch_bounds__(256) void transpose_cvt_kernel(
    const float* __restrict__ Wq, const float* __restrict__ Wk,
    const float* __restrict__ Wv, const float* __restrict__ Wo)
{
    const float* __restrict__ src =
        (blockIdx.z == 0) ? Wq : (blockIdx.z == 1) ? Wk : (blockIdx.z == 2) ? Wv : Wo;
    __shared__ float t[32][33];
    const int tx = threadIdx.x & 31, ty = threadIdx.x >> 5;
    const int k0 = blockIdx.x * 32, n0 = blockIdx.y * 32;
    #pragma unroll
    for (int i = 0; i < 4; ++i) {
        int r = ty + i * 8;
        t[r][tx] = src[(size_t)(k0 + r) * EMB + n0 + tx];
    }
    __syncthreads();
    const size_t base = (size_t)blockIdx.z * EMB * EMB;
    #pragma unroll
    for (int i = 0; i < 4; ++i) {
        int r = ty + i * 8;
        float a = t[tx][r];
        unsigned short h, l;
        split2(a, h, l);
        size_t o = base + (size_t)(n0 + r) * EMB + k0 + tx;
        g_wth[o] = __ushort_as_bfloat16(h);
        g_wtl[o] = __ushort_as_bfloat16(l);
    }
}

// ---------------------------------------------------------------------------
// split-bf16 HMMA GEMM, 2-stage cp.async pipeline (verified R9, unchanged)
// ---------------------------------------------------------------------------
#define GSTAGE 65536
#define GA_HI  0
#define GA_LO  16384
#define GB_HI  32768
#define GB_LO  49152
#define SMEM_DYN (2 * GSTAGE)

__global__ __launch_bounds__(256, 1) void mma_gemm_kernel(
    const float* __restrict__ b0i, const float* __restrict__ b1i,
    const float* __restrict__ b2i, float* __restrict__ out0, int mode)
{
    extern __shared__ char smem[];
    const int tid = threadIdx.x, wid = tid >> 5, lid = tid & 31;
    const int n0 = blockIdx.x * 128, m0 = blockIdx.y * 128;
    const int z = blockIdx.z;

    const __nv_bfloat16 *Ah, *Al, *Bh, *Bl;
    const float* bias;
    if (mode == 0) {
        Ah = g_xh; Al = g_xl;
        Bh = g_wth + (size_t)z * EMB * EMB;
        Bl = g_wtl + (size_t)z * EMB * EMB;
        bias = (z == 0) ? b0i : (z == 1) ? b1i : b2i;
    } else {
        Ah = g_ah; Al = g_al;
        Bh = g_wth + 3ull * EMB * EMB;
        Bl = g_wtl + 3ull * EMB * EMB;
        bias = b0i;
    }

    const uint32_t sb = smem_u32(smem);
    const int wm0 = (wid >> 2) * 64;
    const int wn0 = (wid & 3) * 32;

    const int lr = tid >> 3;
    const int lc = tid & 7;

    {
        #pragma unroll
        for (int i = 0; i < 4; ++i) {
            const int r = lr + i * 32;
            const uint32_t sw = swz((uint32_t)(r * 128 + lc * 16));
            const size_t ga = (size_t)(m0 + r) * EMB + lc * 8;
            const size_t gb = (size_t)(n0 + r) * EMB + lc * 8;
            cp16(sb + GA_HI + sw, Ah + ga);
            cp16(sb + GA_LO + sw, Al + ga);
            cp16(sb + GB_HI + sw, Bh + gb);
            cp16(sb + GB_LO + sw, Bl + gb);
        }
        CP_COMMIT();
    }

    float acc[4][4][4] = {};

    for (int ch = 0; ch < 16; ++ch) {
        if (ch < 15) {
            const uint32_t st = sb + ((ch + 1) & 1) * GSTAGE;
            const int k0n = (ch + 1) * 64;
            #pragma unroll
            for (int i = 0; i < 4; ++i) {
                const int r = lr + i * 32;
                const uint32_t sw = swz((uint32_t)(r * 128 + lc * 16));
                const size_t ga = (size_t)(m0 + r) * EMB + k0n + lc * 8;
                const size_t gb = (size_t)(n0 + r) * EMB + k0n + lc * 8;
                cp16(st + GA_HI + sw, Ah + ga);
                cp16(st + GA_LO + sw, Al + ga);
                cp16(st + GB_HI + sw, Bh + gb);
                cp16(st + GB_LO + sw, Bl + gb);
            }
            CP_COMMIT();
            CP_WAIT(1);
        } else {
            CP_WAIT(0);
        }
        __syncthreads();

        const uint32_t cs = sb + (ch & 1) * GSTAGE;
        #pragma unroll
        for (int k16 = 0; k16 < 4; ++k16) {
            const uint32_t colB = (uint32_t)(k16 * 32 + (lid >> 4) * 16);
            uint32_t bh[4][2], bl[4][2];
            #pragma unroll
            for (int p = 0; p < 2; ++p) {
                const uint32_t off = swz((uint32_t)((wn0 + p * 16 + (lid & 15)) * 128) + colB);
                uint32_t r0, r1, r2, r3;
                ldsm_x4(r0, r1, r2, r3, cs + GB_HI + off);
                bh[2*p][0] = r0; bh[2*p][1] = r2;
                bh[2*p+1][0] = r1; bh[2*p+1][1] = r3;
                ldsm_x4(r0, r1, r2, r3, cs + GB_LO + off);
                bl[2*p][0] = r0; bl[2*p][1] = r2;
                bl[2*p+1][0] = r1; bl[2*p+1][1] = r3;
            }
            #pragma unroll
            for (int mi = 0; mi < 4; ++mi) {
                const uint32_t offA = swz((uint32_t)((wm0 + mi * 16 + (lid & 15)) * 128) + colB);
                uint32_t ahf[4], alf[4];
                ldsm_x4(ahf[0], ahf[1], ahf[2], ahf[3], cs + GA_HI + offA);
                ldsm_x4(alf[0], alf[1], alf[2], alf[3], cs + GA_LO + offA);
                #pragma unroll
                for (int ni = 0; ni < 4; ++ni) {
                    mma_bf16(acc[mi][ni], ahf, bh[ni][0], bh[ni][1]);
                    mma_bf16(acc[mi][ni], ahf, bl[ni][0], bl[ni][1]);
                    mma_bf16(acc[mi][ni], alf, bh[ni][0], bh[ni][1]);
                }
            }
        }
        __syncthreads();
    }

    const int rr = lid >> 2;
    const int cc = (lid & 3) * 2;
    const float sc = (mode == 0 && z == 0) ? 0.125f : 1.0f;
    #pragma unroll
    for (int mi = 0; mi < 4; ++mi) {
        #pragma unroll
        for (int ni = 0; ni < 4; ++ni) {
            const int gcol = n0 + wn0 + ni * 8 + cc;
            const float bx = bias[gcol], by = bias[gcol + 1];
            #pragma unroll
            for (int half = 0; half < 2; ++half) {
                const int m = m0 + wm0 + mi * 16 + rr + half * 8;
                float ox = (acc[mi][ni][half * 2 + 0] + bx) * sc;
                float oy = (acc[mi][ni][half * 2 + 1] + by) * sc;
                if (mode == 0) {
                    const int bb = m >> 11, nn = m & 2047;
                    const int hh = gcol >> 6, dd = gcol & 63;
                    unsigned short hx, lx, hy, ly;
                    split2(ox, hx, lx); split2(oy, hy, ly);
                    const size_t a = ((size_t)(bb * HEADS + hh) * SEQ + nn) * HD + dd;
                    __nv_bfloat16* gh = (z == 0) ? g_qh : (z == 1) ? g_kh : g_vh;
                    __nv_bfloat16* gl = (z == 0) ? g_ql : (z == 1) ? g_kl : g_vl;
                    *(uint32_t*)&gh[a] = (uint32_t)hx | ((uint32_t)hy << 16);
                    *(uint32_t*)&gl[a] = (uint32_t)lx | ((uint32_t)ly << 16);
                } else {
                    float2 o; o.x = ox; o.y = oy;
                    *(float2*)&out0[(size_t)m * EMB + gcol] = o;
                }
            }
        }
    }
}

// ---------------------------------------------------------------------------
// HMMA flash attention, R10: K/V tile 64 rows -> 96KB smem -> 2 CTAs/SM.
// Stage = Kh(8K)+Kl(8K)+Vh(8K)+Vl(8K) = 32KB, double buffered; Q 32KB.
// ---------------------------------------------------------------------------
#define AQ_HI 0
#define AQ_LO 16384
#define ASTG  32768
#define ABUF(b) (32768 + (b) * ASTG)    // +0 Khi, +8192 Klo, +16384 Vhi, +24576 Vlo
#define ATT_SMEM (32768 + 2 * ASTG)     // 96 KB

__global__ __launch_bounds__(256, 2) void attention_mma_kernel()
{
    extern __shared__ char smem[];
    const uint32_t sb = smem_u32(smem);
    const int tid = threadIdx.x, wid = tid >> 5, lid = tid & 31;
    const int qt = blockIdx.x, h = blockIdx.y, b = blockIdx.z;
    const size_t base = (size_t)((b * HEADS + h) * SEQ) * HD;
    const int qrow0 = qt * 128;

    // Q tile (128 rows) + K/V tile 0 (64 rows)
    #pragma unroll
    for (int i = 0; i < 4; ++i) {
        const int idx = tid + i * 256;
        const int r = idx >> 3, c = idx & 7;
        const uint32_t sw = swz((uint32_t)(r * 128 + c * 16));
        const size_t gq = base + (size_t)(qrow0 + r) * HD + c * 8;
        cp16(sb + AQ_HI + sw, g_qh + gq);
        cp16(sb + AQ_LO + sw, g_ql + gq);
    }
    #pragma unroll
    for (int i = 0; i < 2; ++i) {
        const int idx = tid + i * 256;
        const int r = idx >> 3, c = idx & 7;
        const uint32_t sw = swz((uint32_t)(r * 128 + c * 16));
        const size_t gk = base + (size_t)r * HD + c * 8;
        cp16(sb + ABUF(0) +     0 + sw, g_kh + gk);
        cp16(sb + ABUF(0) +  8192 + sw, g_kl + gk);
        cp16(sb + ABUF(0) + 16384 + sw, g_vh + gk);
        cp16(sb + ABUF(0) + 24576 + sw, g_vl + gk);
    }
    CP_COMMIT();

    const int rr = lid >> 2;
    const int cc = (lid & 3) * 2;

    float m0r = -INFINITY, m1r = -INFINITY, l0r = 0.f, l1r = 0.f;
    float acc_o[8][4] = {};

    for (int kt = 0; kt < 32; ++kt) {
        __syncthreads();
        if (kt < 31) {
            const int nb = (kt + 1) & 1;
            #pragma unroll
            for (int i = 0; i < 2; ++i) {
                const int idx = tid + i * 256;
                const int r = idx >> 3, c = idx & 7;
                const uint32_t sw = swz((uint32_t)(r * 128 + c * 16));
                const size_t gk = base + (size_t)((kt + 1) * 64 + r) * HD + c * 8;
                cp16(sb + ABUF(nb) +     0 + sw, g_kh + gk);
                cp16(sb + ABUF(nb) +  8192 + sw, g_kl + gk);
                cp16(sb + ABUF(nb) + 16384 + sw, g_vh + gk);
                cp16(sb + ABUF(nb) + 24576 + sw, g_vl + gk);
            }
            CP_COMMIT();
            CP_WAIT(1);
        } else {
            CP_WAIT(0);
        }
        __syncthreads();

        const uint32_t KH = sb + ABUF(kt & 1);
        const uint32_t KL = KH + 8192;
        const uint32_t VH = KH + 16384;
        const uint32_t VL = KH + 24576;

        // ---- S = Q K^T over 64 K-rows ----
        float s[8][4];
        #pragma unroll
        for (int ni = 0; ni < 8; ++ni)
            #pragma unroll
            for (int c = 0; c < 4; ++c) s[ni][c] = 0.f;

        #pragma unroll
        for (int k16 = 0; k16 < 4; ++k16) {
            const uint32_t colB = (uint32_t)(k16 * 32 + (lid >> 4) * 16);
            const uint32_t offA = swz((uint32_t)((wid * 16 + (lid & 15)) * 128) + colB);
            uint32_t qh[4], ql[4];
            ldsm_x4(qh[0], qh[1], qh[2], qh[3], sb + AQ_HI + offA);
            ldsm_x4(ql[0], ql[1], ql[2], ql[3], sb + AQ_LO + offA);
            #pragma unroll
            for (int t = 0; t < 4; ++t) {
                const uint32_t offB = swz((uint32_t)((t * 16 + (lid & 15)) * 128) + colB);
                uint32_t r0, r1, r2, r3, u0, u1, u2, u3;
                ldsm_x4(r0, r1, r2, r3, KH + offB);
                ldsm_x4(u0, u1, u2, u3, KL + offB);
                mma_bf16(s[2*t],   qh, r0, r2);
                mma_bf16(s[2*t],   ql, r0, r2);
                mma_bf16(s[2*t],   qh, u0, u2);
                mma_bf16(s[2*t+1], qh, r1, r3);
                mma_bf16(s[2*t+1], ql, r1, r3);
                mma_bf16(s[2*t+1], qh, u1, u3);
            }
        }

        // ---- online softmax ----
        float mx0 = -INFINITY, mx1 = -INFINITY;
        #pragma unroll
        for (int ni = 0; ni < 8; ++ni) {
            mx0 = fmaxf(mx0, fmaxf(s[ni][0], s[ni][1]));
            mx1 = fmaxf(mx1, fmaxf(s[ni][2], s[ni][3]));
        }
        #pragma unroll
        for (int msk = 1; msk <= 2; msk <<= 1) {
            mx0 = fmaxf(mx0, __shfl_xor_sync(0xffffffffu, mx0, msk));
            mx1 = fmaxf(mx1, __shfl_xor_sync(0xffffffffu, mx1, msk));
        }
        const float mn0 = fmaxf(m0r, mx0), mn1 = fmaxf(m1r, mx1);
        const float al0 = __expf(m0r - mn0), al1 = __expf(m1r - mn1);
        m0r = mn0; m1r = mn1;
        float sum0 = 0.f, sum1 = 0.f;
        #pragma unroll
        for (int ni = 0; ni < 8; ++ni) {
            s[ni][0] = __expf(s[ni][0] - mn0); sum0 += s[ni][0];
            s[ni][1] = __expf(s[ni][1] - mn0); sum0 += s[ni][1];
            s[ni][2] = __expf(s[ni][2] - mn1); sum1 += s[ni][2];
            s[ni][3] = __expf(s[ni][3] - mn1); sum1 += s[ni][3];
        }
        #pragma unroll
        for (int msk = 1; msk <= 2; msk <<= 1) {
            sum0 += __shfl_xor_sync(0xffffffffu, sum0, msk);
            sum1 += __shfl_xor_sync(0xffffffffu, sum1, msk);
        }
        l0r = l0r * al0 + sum0;
        l1r = l1r * al1 + sum1;
        #pragma unroll
        for (int di = 0; di < 8; ++di) {
            acc_o[di][0] *= al0; acc_o[di][1] *= al0;
            acc_o[di][2] *= al1; acc_o[di][3] *= al1;
        }

        // ---- O += P V over 64 V-rows ----
        #pragma unroll
        for (int jj = 0; jj < 4; ++jj) {
            uint32_t ph[4], pl[4];
            #pragma unroll
            for (int e = 0; e < 2; ++e) {
                const int ni = 2 * jj + e;
                float p0 = s[ni][0], p1 = s[ni][1], p2 = s[ni][2], p3 = s[ni][3];
                __nv_bfloat16 h0 = __float2bfloat16_rn(p0), h1 = __float2bfloat16_rn(p1);
                __nv_bfloat16 h2 = __float2bfloat16_rn(p2), h3 = __float2bfloat16_rn(p3);
                ph[2*e]   = packlh(p0, p1);
                ph[2*e+1] = packlh(p2, p3);
                pl[2*e]   = packlh(p0 - __bfloat162float(h0), p1 - __bfloat162float(h1));
                pl[2*e+1] = packlh(p2 - __bfloat162float(h2), p3 - __bfloat162float(h3));
            }
            #pragma unroll
            for (int dt = 0; dt < 4; ++dt) {
                const uint32_t va = swz((uint32_t)((jj * 16 + (lid & 15)) * 128 +
                                                   dt * 32 + (lid >> 4) * 16));
                uint32_t v0, v1, v2, v3, w0, w1, w2, w3;
                ldsm_x4_t(v0, v1, v2, v3, VH + va);
                ldsm_x4_t(w0, w1, w2, w3, VL + va);
                mma_bf16(acc_o[2*dt],   ph, v0, v1);
                mma_bf16(acc_o[2*dt],   pl, v0, v1);
                mma_bf16(acc_o[2*dt],   ph, w0, w1);
                mma_bf16(acc_o[2*dt+1], ph, v2, v3);
                mma_bf16(acc_o[2*dt+1], pl, v2, v3);
                mma_bf16(acc_o[2*dt+1], ph, w2, w3);
            }
        }
    }

    // ---- epilogue ----
    const float inv0 = 1.0f / l0r, inv1 = 1.0f / l1r;
    const int i0 = qrow0 + wid * 16 + rr;
    #pragma unroll
    for (int di = 0; di < 8; ++di) {
        const int col = h * HD + di * 8 + cc;
        {
            float ox = acc_o[di][0] * inv0, oy = acc_o[di][1] * inv0;
            unsigned short hx, lx, hy, ly;
            split2(ox, hx, lx); split2(oy, hy, ly);
            const size_t a = ((size_t)(b * SEQ) + i0) * EMB + col;
            *(uint32_t*)&g_ah[a] = (uint32_t)hx | ((uint32_t)hy << 16);
            *(uint32_t*)&g_al[a] = (uint32_t)lx | ((uint32_t)ly << 16);
        }
        {
            float ox = acc_o[di][2] * inv1, oy = acc_o[di][3] * inv1;
            unsigned short hx, lx, hy, ly;
            split2(ox, hx, lx); split2(oy, hy, ly);
            const size_t a = ((size_t)(b * SEQ) + i0 + 8) * EMB + col;
            *(uint32_t*)&g_ah[a] = (uint32_t)hx | ((uint32_t)hy << 16);
            *(uint32_t*)&g_al[a] = (uint32_t)lx | ((uint32_t)ly << 16);
        }
    }
}

// ---------------------------------------------------------------------------
// Dispatch (robust size-class mapping, proven R4-R9)
// ---------------------------------------------------------------------------
extern "C" void kernel_launch(void* const* d_in, const int* in_sizes, int n_in,
                              void* d_out, int out_size)
{
    (void)out_size;

    long long scale = 1;
    for (int i = 0; i < n_in; ++i)
        if ((long long)in_sizes[i] == 16777216LL) { scale = 4; break; }

    const float* x  = (const float*)d_in[0];
    const float* Wenc[4] = { (const float*)d_in[1], (const float*)d_in[3],
                             (const float*)d_in[5], (const float*)d_in[7] };
    const float* benc[4] = { (const float*)d_in[2], (const float*)d_in[4],
                             (const float*)d_in[6], (const float*)d_in[8] };
    int wIdx[4] = { 1, 3, 5, 7 };
    int nw = 0, nb = 0;

    for (int i = 0; i < n_in; ++i) {
        long long elems = (long long)in_sizes[i] / scale;
        if (elems == (long long)BATCH * SEQ * EMB) {
            x = (const float*)d_in[i];
        } else if (elems == (long long)EMB * EMB) {
            if (nw < 4) { wIdx[nw] = i; Wenc[nw] = (const float*)d_in[i]; }
            ++nw;
        } else if (elems == (long long)EMB) {
            if (nb < 4) { benc[nb] = (const float*)d_in[i]; }
            ++nb;
        }
    }

    bool sortedLayout = false;
    if (nw == 4 && nb == 4)
        sortedLayout = (wIdx[1] == wIdx[0] + 1) &&
                       (wIdx[2] == wIdx[1] + 1) &&
                       (wIdx[3] == wIdx[2] + 1);

    const float *Wq, *Wk, *Wv, *Wo, *bq, *bk, *bv, *bo;
    if (sortedLayout) {
        Wk = Wenc[0]; Wo = Wenc[1]; Wq = Wenc[2]; Wv = Wenc[3];
        bk = benc[0]; bo = benc[1]; bq = benc[2]; bv = benc[3];
    } else {
        Wq = Wenc[0]; Wk = Wenc[1]; Wv = Wenc[2]; Wo = Wenc[3];
        bq = benc[0]; bk = benc[1]; bv = benc[2]; bo = benc[3];
    }

    float* out = (float*)d_out;

    cudaFuncSetAttribute(mma_gemm_kernel,
                         cudaFuncAttributeMaxDynamicSharedMemorySize, SMEM_DYN);
    cudaFuncSetAttribute(attention_mma_kernel,
                         cudaFuncAttributeMaxDynamicSharedMemorySize, ATT_SMEM);

    cvt_x_kernel<<<MROWS * EMB / 1024, 256>>>(x);
    transpose_cvt_kernel<<<dim3(EMB / 32, EMB / 32, 4), 256>>>(Wq, Wk, Wv, Wo);

    mma_gemm_kernel<<<dim3(EMB / 128, MROWS / 128, 3), 256, SMEM_DYN>>>(
        bq, bk, bv, nullptr, 0);

    attention_mma_kernel<<<dim3(SEQ / 128, HEADS, BATCH), 256, ATT_SMEM>>>();

    mma_gemm_kernel<<<dim3(EMB / 128, MROWS / 128, 1), 256, SMEM_DYN>>>(
        bo, bo, bo, out, 1);
}